// round 1
// baseline (speedup 1.0000x reference)
#include <cuda_runtime.h>
#include <cuda_bf16.h>
#include <math.h>

// Problem constants
#define BATCH   2
#define S_LEN   2048
#define NHEAD   16
#define HD      64
#define DMODEL  1024   // NHEAD*HD
#define NPAIRS  32     // HD/2

// Scratch (device globals — no allocation allowed)
__device__ float g_Q[BATCH*NHEAD*S_LEN*HD];
__device__ float g_K[BATCH*NHEAD*S_LEN*HD];
__device__ float g_V[BATCH*NHEAD*S_LEN*HD];
__device__ float g_attn[BATCH*S_LEN*DMODEL];
__device__ int   g_pos[BATCH*S_LEN*3];
__device__ int   g_is64;
__device__ float g_cos[NPAIRS*32];
__device__ float g_sin[NPAIRS*32];

#define NEGINF __int_as_float(0xff800000)

// ---------------------------------------------------------------------------
// Position dtype detection: if pos_xyz arrived as int64, every odd 32-bit word
// (high half of a small nonnegative value) is 0. Only reads the first
// n_words int32s, which is safe under both layouts.
// ---------------------------------------------------------------------------
__global__ void detect_pos64(const int* __restrict__ raw, int n_words) {
    __shared__ int red[256];
    int acc = 0;
    for (int i = threadIdx.x; 2*i + 1 < n_words; i += 256)
        acc |= raw[2*i + 1];
    red[threadIdx.x] = acc;
    __syncthreads();
    for (int s1 = 128; s1 > 0; s1 >>= 1) {
        if (threadIdx.x < s1) red[threadIdx.x] |= red[threadIdx.x + s1];
        __syncthreads();
    }
    if (threadIdx.x == 0) g_is64 = (red[0] == 0) ? 1 : 0;
}

__global__ void convert_pos(const int* __restrict__ raw, int n) {
    int i = blockIdx.x * 256 + threadIdx.x;
    if (i >= n) return;
    int v = g_is64 ? raw[2*i] : raw[i];
    int ax = i % 3;
    int mx = (ax == 0) ? 31 : (ax == 1 ? 31 : 7);
    v = v < 0 ? 0 : (v > mx ? mx : v);
    g_pos[i] = v;
}

// ---------------------------------------------------------------------------
// RoPE cos/sin tables. _split_dims(64) -> dx=20 (pairs 0..9), dy=20 (10..19),
// dz=24 (20..31). Table indexed [pair][pos].
// ---------------------------------------------------------------------------
__global__ void build_tables() {
    int t = threadIdx.x;            // 1024 threads
    int p = t >> 5, pos = t & 31;
    float inv;
    if (p < 10)      inv = powf(10000.0f, -(2.0f * p)        / 20.0f);
    else if (p < 20) inv = powf(10000.0f, -(2.0f * (p - 10)) / 20.0f);
    else             inv = powf(10000.0f, -(2.0f * (p - 20)) / 24.0f);
    float ang = (float)pos * inv;
    g_cos[t] = cosf(ang);
    g_sin[t] = sinf(ang);
}

// ---------------------------------------------------------------------------
// SGEMM 128x128x16, 8x8 per thread, 256 threads.
// mode 0: C = A@B plain          (unused this round)
// mode 1: scatter into g_Q/g_K/g_V with [b,h,s,d] layout (QKV projection)
// mode 2: A = g_attn, C plain    (output projection)
// ---------------------------------------------------------------------------
#define BM 128
#define BN 128
#define BK 16

__global__ __launch_bounds__(256)
void sgemm_kernel(const float* __restrict__ Aarg, const float* __restrict__ B,
                  float* __restrict__ C, int M, int N, int K, int mode)
{
    __shared__ float As[BK*(BM+4)];   // transposed: As[k][m]
    __shared__ float Bs[BK*BN];       // Bs[k][n]
    const float* A = (mode == 2) ? (const float*)g_attn : Aarg;

    const int tid = threadIdx.x;
    const int tx = tid & 15, ty = tid >> 4;
    const int m0 = blockIdx.y * BM;
    const int n0 = blockIdx.x * BN;

    float acc[8][8] = {};

    for (int k0 = 0; k0 < K; k0 += BK) {
        // global loads first (overlap with previous compute before the sync)
        const int ar  = tid >> 2,        ac  = (tid & 3) << 2;
        const int ar2 = (tid + 256) >> 2, ac2 = ((tid + 256) & 3) << 2;
        const int br  = tid >> 5,        bc  = (tid & 31) << 2;
        const int br2 = (tid + 256) >> 5, bc2 = ((tid + 256) & 31) << 2;
        float4 a0 = *(const float4*)(A + (m0 + ar )*K + k0 + ac );
        float4 a1 = *(const float4*)(A + (m0 + ar2)*K + k0 + ac2);
        float4 b0 = *(const float4*)(B + (k0 + br )*N + n0 + bc );
        float4 b1 = *(const float4*)(B + (k0 + br2)*N + n0 + bc2);

        __syncthreads();   // previous tile fully consumed
        As[(ac +0)*(BM+4) + ar ] = a0.x;
        As[(ac +1)*(BM+4) + ar ] = a0.y;
        As[(ac +2)*(BM+4) + ar ] = a0.z;
        As[(ac +3)*(BM+4) + ar ] = a0.w;
        As[(ac2+0)*(BM+4) + ar2] = a1.x;
        As[(ac2+1)*(BM+4) + ar2] = a1.y;
        As[(ac2+2)*(BM+4) + ar2] = a1.z;
        As[(ac2+3)*(BM+4) + ar2] = a1.w;
        *(float4*)(Bs + br *BN + bc ) = b0;
        *(float4*)(Bs + br2*BN + bc2) = b1;
        __syncthreads();

        #pragma unroll
        for (int kk = 0; kk < BK; ++kk) {
            float a[8], b[8];
            *(float4*)(a)     = *(const float4*)(As + kk*(BM+4) + ty*8);
            *(float4*)(a + 4) = *(const float4*)(As + kk*(BM+4) + ty*8 + 4);
            *(float4*)(b)     = *(const float4*)(Bs + kk*BN + tx*8);
            *(float4*)(b + 4) = *(const float4*)(Bs + kk*BN + tx*8 + 4);
            #pragma unroll
            for (int i = 0; i < 8; ++i)
                #pragma unroll
                for (int j = 0; j < 8; ++j)
                    acc[i][j] += a[i] * b[j];
        }
    }

    if (mode == 1) {
        // scatter qkv output (m = b*S+s, n -> sec,h,d) into [b,h,s,d]
        #pragma unroll
        for (int i = 0; i < 8; ++i) {
            int m = m0 + ty*8 + i;
            int bb = m >> 11, s = m & 2047;
            #pragma unroll
            for (int j = 0; j < 8; ++j) {
                int n = n0 + tx*8 + j;
                int sec = n >> 10;
                int r = n & 1023;
                int h = r >> 6, d = r & 63;
                int idx = ((bb*NHEAD + h)*S_LEN + s)*HD + d;
                float* dst = (sec == 0) ? g_Q : ((sec == 1) ? g_K : g_V);
                dst[idx] = acc[i][j];
            }
        }
    } else {
        #pragma unroll
        for (int i = 0; i < 8; ++i) {
            int m = m0 + ty*8 + i;
            *(float4*)(C + m*N + n0 + tx*8)     = make_float4(acc[i][0], acc[i][1], acc[i][2], acc[i][3]);
            *(float4*)(C + m*N + n0 + tx*8 + 4) = make_float4(acc[i][4], acc[i][5], acc[i][6], acc[i][7]);
        }
    }
}

// ---------------------------------------------------------------------------
// RoPE applied in-place to Q and K. One thread per (b,s,pair); loops heads
// (cos/sin shared across heads).
// ---------------------------------------------------------------------------
__global__ void rope_kernel() {
    int idx = blockIdx.x * blockDim.x + threadIdx.x;  // < BATCH*S_LEN*NPAIRS
    int p = idx & 31;
    int t = idx >> 5;                                 // token 0..4095
    if (t >= BATCH * S_LEN) return;
    int b = t >> 11, s = t & 2047;
    int ax = (p < 10) ? 0 : ((p < 20) ? 1 : 2);
    int pos = g_pos[t*3 + ax];
    float c  = g_cos[p*32 + pos];
    float sn = g_sin[p*32 + pos];
    int base = ((b*NHEAD)*S_LEN + s)*HD + 2*p;
    #pragma unroll 4
    for (int h = 0; h < NHEAD; ++h) {
        int off = base + h * (S_LEN * HD);
        float2 q = *(float2*)(g_Q + off);
        float2 k = *(float2*)(g_K + off);
        float2 qo = make_float2(q.x*c - q.y*sn, q.y*c + q.x*sn);
        float2 ko = make_float2(k.x*c - k.y*sn, k.y*c + k.x*sn);
        *(float2*)(g_Q + off) = qo;
        *(float2*)(g_K + off) = ko;
    }
}

// ---------------------------------------------------------------------------
// Flash attention (causal). Block = (qtile of 64 rows) x (one b,h).
// 256 threads as 16x16; each thread owns a 4x4 microtile.
// Smem: Qs[d][r], KPs[d][c] (reused for P^T[k][r]), Vs[k][c]; stride 72.
// ---------------------------------------------------------------------------
#define AST 72
#define ATILE 64

__global__ __launch_bounds__(256)
void attention_kernel() {
    extern __shared__ float sm[];
    float* Qs  = sm;                  // [64][72], d-major (transposed)
    float* KPs = sm + ATILE*AST;      // K transposed, then P^T
    float* Vs  = sm + 2*ATILE*AST;    // [k][c] natural

    const int tid = threadIdx.x;
    const int tx = tid & 15, ty = tid >> 4;
    const int bh = blockIdx.y;
    const int qt = (int)gridDim.x - 1 - (int)blockIdx.x;  // big tiles first

    const float* Qg = g_Q + (bh*S_LEN + qt*ATILE)*HD;

    // Load Q tile, transpose into Qs[d][r]
    for (int f = tid; f < ATILE*HD/4; f += 256) {
        int row = f >> 4, c4 = (f & 15) << 2;
        float4 v = *(const float4*)(Qg + row*HD + c4);
        Qs[(c4+0)*AST + row] = v.x;
        Qs[(c4+1)*AST + row] = v.y;
        Qs[(c4+2)*AST + row] = v.z;
        Qs[(c4+3)*AST + row] = v.w;
    }

    float o[4][4] = {};
    float mrow[4], lrow[4];
    #pragma unroll
    for (int i = 0; i < 4; ++i) { mrow[i] = NEGINF; lrow[i] = 0.0f; }

    for (int kt = 0; kt <= qt; ++kt) {
        __syncthreads();  // prev PV done (and Q load done on first iter)

        const float* Kg = g_K + (bh*S_LEN + kt*ATILE)*HD;
        const float* Vg = g_V + (bh*S_LEN + kt*ATILE)*HD;
        for (int f = tid; f < ATILE*HD/4; f += 256) {
            int row = f >> 4, c4 = (f & 15) << 2;
            float4 kv = *(const float4*)(Kg + row*HD + c4);
            KPs[(c4+0)*AST + row] = kv.x;
            KPs[(c4+1)*AST + row] = kv.y;
            KPs[(c4+2)*AST + row] = kv.z;
            KPs[(c4+3)*AST + row] = kv.w;
            float4 vv = *(const float4*)(Vg + row*HD + c4);
            *(float4*)(Vs + row*AST + c4) = vv;
        }
        __syncthreads();

        // S = Q K^T  (4x4 per thread)
        float acc[4][4] = {};
        #pragma unroll 8
        for (int d = 0; d < HD; ++d) {
            float4 q = *(const float4*)(Qs  + d*AST + (ty << 2));
            float4 k = *(const float4*)(KPs + d*AST + (tx << 2));
            acc[0][0] += q.x*k.x; acc[0][1] += q.x*k.y; acc[0][2] += q.x*k.z; acc[0][3] += q.x*k.w;
            acc[1][0] += q.y*k.x; acc[1][1] += q.y*k.y; acc[1][2] += q.y*k.z; acc[1][3] += q.y*k.w;
            acc[2][0] += q.z*k.x; acc[2][1] += q.z*k.y; acc[2][2] += q.z*k.z; acc[2][3] += q.z*k.w;
            acc[3][0] += q.w*k.x; acc[3][1] += q.w*k.y; acc[3][2] += q.w*k.z; acc[3][3] += q.w*k.w;
        }
        __syncthreads();  // everyone done reading KPs (about to become P^T)

        const bool diag = (kt == qt);
        #pragma unroll
        for (int i = 0; i < 4; ++i)
            #pragma unroll
            for (int j = 0; j < 4; ++j) {
                if (diag && ((tx << 2) + j > (ty << 2) + i)) acc[i][j] = NEGINF;
                else acc[i][j] *= 0.125f;   // Hd^-0.5
            }

        // online softmax per row (row spread across 16 tx lanes, width-16 shfl)
        #pragma unroll
        for (int i = 0; i < 4; ++i) {
            float rm = fmaxf(fmaxf(acc[i][0], acc[i][1]), fmaxf(acc[i][2], acc[i][3]));
            #pragma unroll
            for (int off = 8; off > 0; off >>= 1)
                rm = fmaxf(rm, __shfl_xor_sync(0xffffffffu, rm, off, 16));
            float mnew = fmaxf(mrow[i], rm);
            float corr = __expf(mrow[i] - mnew);
            float rs = 0.0f;
            #pragma unroll
            for (int j = 0; j < 4; ++j) {
                acc[i][j] = __expf(acc[i][j] - mnew);
                rs += acc[i][j];
            }
            #pragma unroll
            for (int off = 8; off > 0; off >>= 1)
                rs += __shfl_xor_sync(0xffffffffu, rs, off, 16);
            lrow[i] = lrow[i] * corr + rs;
            mrow[i] = mnew;
            o[i][0] *= corr; o[i][1] *= corr; o[i][2] *= corr; o[i][3] *= corr;
        }

        // store P transposed: P^T[k][r]
        #pragma unroll
        for (int i = 0; i < 4; ++i)
            #pragma unroll
            for (int j = 0; j < 4; ++j)
                KPs[((tx << 2) + j)*AST + (ty << 2) + i] = acc[i][j];
        __syncthreads();

        // O += P V
        #pragma unroll 8
        for (int k2 = 0; k2 < ATILE; ++k2) {
            float4 pp = *(const float4*)(KPs + k2*AST + (ty << 2));
            float4 vv = *(const float4*)(Vs  + k2*AST + (tx << 2));
            o[0][0] += pp.x*vv.x; o[0][1] += pp.x*vv.y; o[0][2] += pp.x*vv.z; o[0][3] += pp.x*vv.w;
            o[1][0] += pp.y*vv.x; o[1][1] += pp.y*vv.y; o[1][2] += pp.y*vv.z; o[1][3] += pp.y*vv.w;
            o[2][0] += pp.z*vv.x; o[2][1] += pp.z*vv.y; o[2][2] += pp.z*vv.z; o[2][3] += pp.z*vv.w;
            o[3][0] += pp.w*vv.x; o[3][1] += pp.w*vv.y; o[3][2] += pp.w*vv.z; o[3][3] += pp.w*vv.w;
        }
    }

    // epilogue: write [b, s, h*64+d]
    const int b = bh >> 4, h = bh & 15;
    #pragma unroll
    for (int i = 0; i < 4; ++i) {
        float inv = 1.0f / lrow[i];
        int sg = qt*ATILE + (ty << 2) + i;
        float4 r = make_float4(o[i][0]*inv, o[i][1]*inv, o[i][2]*inv, o[i][3]*inv);
        *(float4*)(g_attn + (b*S_LEN + sg)*DMODEL + h*HD + (tx << 2)) = r;
    }
}

// ---------------------------------------------------------------------------
extern "C" void kernel_launch(void* const* d_in, const int* in_sizes, int n_in,
                              void* d_out, int out_size) {
    const float* hs   = (const float*)d_in[0];   // hidden_states [2,2048,1024]
    const float* wqkv = (const float*)d_in[1];   // [1024,3072]
    const float* wout = (const float*)d_in[2];   // [1024,1024]
    const int*   pos  = (const int*)  d_in[3];   // pos_xyz (int32 or int64)
    float* out = (float*)d_out;

    const int n_pos = BATCH * S_LEN * 3;

    detect_pos64<<<1, 256>>>(pos, n_pos);
    convert_pos<<<(n_pos + 255)/256, 256>>>(pos, n_pos);
    build_tables<<<1, 1024>>>();

    // QKV projection + scatter
    sgemm_kernel<<<dim3(3*DMODEL/BN, BATCH*S_LEN/BM), 256>>>(
        hs, wqkv, nullptr, BATCH*S_LEN, 3*DMODEL, DMODEL, 1);

    // RoPE on Q, K
    rope_kernel<<<(BATCH*S_LEN*NPAIRS)/256, 256>>>();

    // Attention
    int smem = 3 * ATILE * AST * (int)sizeof(float);  // 55296 B
    cudaFuncSetAttribute(attention_kernel,
                         cudaFuncAttributeMaxDynamicSharedMemorySize, smem);
    attention_kernel<<<dim3(S_LEN/ATILE, BATCH*NHEAD), 256, smem>>>();

    // Output projection (A = g_attn)
    sgemm_kernel<<<dim3(DMODEL/BN, BATCH*S_LEN/BM), 256>>>(
        hs, wout, out, BATCH*S_LEN, DMODEL, DMODEL, 2);
}

// round 6
// speedup vs baseline: 1.1003x; 1.1003x over previous
#include <cuda_runtime.h>
#include <cuda_bf16.h>
#include <math.h>
#include <stdint.h>

// Problem constants
#define BATCH   2
#define S_LEN   2048
#define NHEAD   16
#define HD      64
#define DMODEL  1024   // NHEAD*HD
#define NPAIRS  32     // HD/2
#define NTOK    (BATCH*S_LEN)   // 4096

typedef unsigned long long ull;

// Scratch (device globals — no allocation allowed)
__device__ float g_Q[BATCH*NHEAD*S_LEN*HD];
__device__ float g_K[BATCH*NHEAD*S_LEN*HD];
__device__ float g_V[BATCH*NHEAD*S_LEN*HD];
__device__ float g_attn[NTOK*DMODEL];
__device__ int   g_pos[NTOK*3];
__device__ int   g_is64;
__device__ float g_cos[NPAIRS*32];
__device__ float g_sin[NPAIRS*32];

#define NEGINF __int_as_float(0xff800000)

// ---------------------------------------------------------------------------
// packed f32x2 helpers (Blackwell FFMA2 — PTX-only path)
// ---------------------------------------------------------------------------
__device__ __forceinline__ void fma2(ull &d, ull a, ull b) {
    asm("fma.rn.f32x2 %0, %1, %2, %0;" : "+l"(d) : "l"(a), "l"(b));
}
__device__ __forceinline__ void mul2(ull &d, ull a, ull b) {
    asm("mul.rn.f32x2 %0, %1, %2;" : "=l"(d) : "l"(a), "l"(b));
}
__device__ __forceinline__ ull pack2(float lo, float hi) {
    ull r;
    asm("mov.b64 %0, {%1, %2};" : "=l"(r) : "r"(__float_as_uint(lo)), "r"(__float_as_uint(hi)));
    return r;
}
__device__ __forceinline__ ull dup2(float x) {
    ull r;
    asm("mov.b64 %0, {%1, %1};" : "=l"(r) : "r"(__float_as_uint(x)));
    return r;
}
__device__ __forceinline__ float2 unpack2(ull v) {
    uint32_t lo, hi;
    asm("mov.b64 {%0, %1}, %2;" : "=r"(lo), "=r"(hi) : "l"(v));
    return make_float2(__uint_as_float(lo), __uint_as_float(hi));
}

// ---------------------------------------------------------------------------
// Position dtype detection + conversion
// ---------------------------------------------------------------------------
__global__ void detect_pos64(const int* __restrict__ raw, int n_words) {
    __shared__ int red[256];
    int acc = 0;
    for (int i = threadIdx.x; 2*i + 1 < n_words; i += 256)
        acc |= raw[2*i + 1];
    red[threadIdx.x] = acc;
    __syncthreads();
    for (int s1 = 128; s1 > 0; s1 >>= 1) {
        if (threadIdx.x < s1) red[threadIdx.x] |= red[threadIdx.x + s1];
        __syncthreads();
    }
    if (threadIdx.x == 0) g_is64 = (red[0] == 0) ? 1 : 0;
}

__global__ void convert_pos(const int* __restrict__ raw, int n) {
    int i = blockIdx.x * 256 + threadIdx.x;
    if (i >= n) return;
    int v = g_is64 ? raw[2*i] : raw[i];
    int ax = i % 3;
    int mx = (ax == 2) ? 7 : 31;
    v = v < 0 ? 0 : (v > mx ? mx : v);
    g_pos[i] = v;
}

__global__ void build_tables() {
    int t = threadIdx.x;            // 1024 threads
    int p = t >> 5, pos = t & 31;
    float inv;
    if (p < 10)      inv = powf(10000.0f, -(2.0f * p)        / 20.0f);
    else if (p < 20) inv = powf(10000.0f, -(2.0f * (p - 10)) / 20.0f);
    else             inv = powf(10000.0f, -(2.0f * (p - 20)) / 24.0f);
    float ang = (float)pos * inv;
    g_cos[t] = cosf(ang);
    g_sin[t] = sinf(ang);
}

// ---------------------------------------------------------------------------
// SGEMM 128x128x16 with packed FFMA2: 256 threads, 8x8 per thread held as
// 4 row-pairs x 8 columns (b duplicated into both halves).
// mode 1: scatter into g_Q/g_K/g_V [b,h,s,d]; mode 2: A = g_attn, plain C.
// ---------------------------------------------------------------------------
#define BM 128
#define BN 128
#define BK 16
#define AS_ST (BM+4)

__global__ __launch_bounds__(256, 2)
void sgemm_kernel(const float* __restrict__ Aarg, const float* __restrict__ B,
                  float* __restrict__ C, int M, int N, int K, int mode)
{
    __shared__ float As[BK*AS_ST];    // transposed: As[k][m]
    __shared__ float Bs[BK*BN];       // Bs[k][n]
    const float* A = (mode == 2) ? (const float*)g_attn : Aarg;

    const int tid = threadIdx.x;
    const int tx = tid & 15, ty = tid >> 4;
    const int m0 = blockIdx.y * BM;
    const int n0 = blockIdx.x * BN;

    ull acc2[4][8];
    #pragma unroll
    for (int i = 0; i < 4; ++i)
        #pragma unroll
        for (int j = 0; j < 8; ++j) acc2[i][j] = 0ull;

    for (int k0 = 0; k0 < K; k0 += BK) {
        const int ar  = tid >> 2,         ac  = (tid & 3) << 2;
        const int ar2 = (tid + 256) >> 2, ac2 = ((tid + 256) & 3) << 2;
        const int br  = tid >> 5,         bc  = (tid & 31) << 2;
        const int br2 = (tid + 256) >> 5, bc2 = ((tid + 256) & 31) << 2;
        float4 a0 = *(const float4*)(A + (size_t)(m0 + ar )*K + k0 + ac );
        float4 a1 = *(const float4*)(A + (size_t)(m0 + ar2)*K + k0 + ac2);
        float4 b0 = *(const float4*)(B + (size_t)(k0 + br )*N + n0 + bc );
        float4 b1 = *(const float4*)(B + (size_t)(k0 + br2)*N + n0 + bc2);

        __syncthreads();   // previous tile fully consumed
        As[(ac +0)*AS_ST + ar ] = a0.x;
        As[(ac +1)*AS_ST + ar ] = a0.y;
        As[(ac +2)*AS_ST + ar ] = a0.z;
        As[(ac +3)*AS_ST + ar ] = a0.w;
        As[(ac2+0)*AS_ST + ar2] = a1.x;
        As[(ac2+1)*AS_ST + ar2] = a1.y;
        As[(ac2+2)*AS_ST + ar2] = a1.z;
        As[(ac2+3)*AS_ST + ar2] = a1.w;
        *(float4*)(Bs + br *BN + bc ) = b0;
        *(float4*)(Bs + br2*BN + bc2) = b1;
        __syncthreads();

        #pragma unroll
        for (int kk = 0; kk < BK; ++kk) {
            const float* arow = As + kk*AS_ST + ty*8;
            ull ap0 = *(const ull*)(arow + 0);
            ull ap1 = *(const ull*)(arow + 2);
            ull ap2 = *(const ull*)(arow + 4);
            ull ap3 = *(const ull*)(arow + 6);
            const float* brow = Bs + kk*BN + tx*8;
            float4 bv0 = *(const float4*)(brow);
            float4 bv1 = *(const float4*)(brow + 4);
            ull bd[8];
            bd[0] = dup2(bv0.x); bd[1] = dup2(bv0.y); bd[2] = dup2(bv0.z); bd[3] = dup2(bv0.w);
            bd[4] = dup2(bv1.x); bd[5] = dup2(bv1.y); bd[6] = dup2(bv1.z); bd[7] = dup2(bv1.w);
            #pragma unroll
            for (int j = 0; j < 8; ++j) {
                fma2(acc2[0][j], ap0, bd[j]);
                fma2(acc2[1][j], ap1, bd[j]);
                fma2(acc2[2][j], ap2, bd[j]);
                fma2(acc2[3][j], ap3, bd[j]);
            }
        }
    }

    if (mode == 1) {
        // scatter qkv output (m = b*S+s, n -> sec,h,d) into [b,h,s,d]
        #pragma unroll
        for (int i2 = 0; i2 < 4; ++i2) {
            int mlo = m0 + ty*8 + 2*i2;
            #pragma unroll
            for (int j = 0; j < 8; ++j) {
                float2 u = unpack2(acc2[i2][j]);
                int n = n0 + tx*8 + j;
                int sec = n >> 10;
                int r = n & 1023;
                int h = r >> 6, d = r & 63;
                float* dst = (sec == 0) ? g_Q : ((sec == 1) ? g_K : g_V);
                int bb = mlo >> 11, s = mlo & 2047;
                dst[((bb*NHEAD + h)*S_LEN + s)*HD + d] = u.x;
                int m2 = mlo + 1;
                bb = m2 >> 11; s = m2 & 2047;
                dst[((bb*NHEAD + h)*S_LEN + s)*HD + d] = u.y;
            }
        }
    } else {
        #pragma unroll
        for (int i2 = 0; i2 < 4; ++i2) {
            float2 u[8];
            #pragma unroll
            for (int j = 0; j < 8; ++j) u[j] = unpack2(acc2[i2][j]);
            int mlo = m0 + ty*8 + 2*i2;
            float* plo = C + (size_t)mlo*N + n0 + tx*8;
            float* phi = plo + N;
            *(float4*)(plo)     = make_float4(u[0].x, u[1].x, u[2].x, u[3].x);
            *(float4*)(plo + 4) = make_float4(u[4].x, u[5].x, u[6].x, u[7].x);
            *(float4*)(phi)     = make_float4(u[0].y, u[1].y, u[2].y, u[3].y);
            *(float4*)(phi + 4) = make_float4(u[4].y, u[5].y, u[6].y, u[7].y);
        }
    }
}

// ---------------------------------------------------------------------------
// RoPE applied in-place to Q and K
// ---------------------------------------------------------------------------
__global__ void rope_kernel() {
    int idx = blockIdx.x * blockDim.x + threadIdx.x;
    int p = idx & 31;
    int t = idx >> 5;
    if (t >= BATCH * S_LEN) return;
    int b = t >> 11, s = t & 2047;
    int ax = (p < 10) ? 0 : ((p < 20) ? 1 : 2);
    int pos = g_pos[t*3 + ax];
    float c  = g_cos[p*32 + pos];
    float sn = g_sin[p*32 + pos];
    int base = ((b*NHEAD)*S_LEN + s)*HD + 2*p;
    #pragma unroll 4
    for (int h = 0; h < NHEAD; ++h) {
        int off = base + h * (S_LEN * HD);
        float2 q = *(float2*)(g_Q + off);
        float2 k = *(float2*)(g_K + off);
        float2 qo = make_float2(q.x*c - q.y*sn, q.y*c + q.x*sn);
        float2 ko = make_float2(k.x*c - k.y*sn, k.y*c + k.x*sn);
        *(float2*)(g_Q + off) = qo;
        *(float2*)(g_K + off) = ko;
    }
}

// ---------------------------------------------------------------------------
// Flash attention (causal), fp32 with FFMA2.
// Tile: 128 q-rows x 64 k-cols per CTA; 256 threads as 16tx x 16ty;
// thread owns 8 q-rows (4 packed pairs) x 4 k-cols.
// Smem: Qs[d][r] stride 130, KTs[d][c] stride 74, PTs[k][r] stride 130,
//       Vs[k][c] stride 72. Strides chosen: transposed STS at 4-way (not 16).
// ---------------------------------------------------------------------------
#define QROWS 128
#define KCOLS 64
#define QST 130
#define KST 74
#define VST 72
#define ATT_SMEM ((64*QST + 64*KST + 64*QST + 64*VST) * 4)   // 103936 B

__global__ __launch_bounds__(256, 2)
void attention_kernel() {
    extern __shared__ float sm[];
    float* Qs  = sm;                    // [64][130] d-major (transposed Q)
    float* KTs = Qs  + 64*QST;          // [64][74]  d-major (transposed K)
    float* PTs = KTs + 64*KST;          // [64][130] k-major (transposed P)
    float* Vs  = PTs + 64*QST;          // [64][72]  natural V

    const int tid = threadIdx.x;
    const int tx = tid & 15, ty = tid >> 4;
    const int bh = blockIdx.y;
    const int qt = (int)gridDim.x - 1 - (int)blockIdx.x;  // big tiles first

    const float* Qg = g_Q + (bh*S_LEN + qt*QROWS)*HD;

    // Load Q tile (128x64), transpose into Qs[d][r]
    #pragma unroll
    for (int it = 0; it < 8; ++it) {
        int f = tid + it*256;           // < 2048
        int row = f >> 4, c4 = (f & 15) << 2;
        float4 v = *(const float4*)(Qg + row*HD + c4);
        Qs[(c4+0)*QST + row] = v.x;
        Qs[(c4+1)*QST + row] = v.y;
        Qs[(c4+2)*QST + row] = v.z;
        Qs[(c4+3)*QST + row] = v.w;
    }

    ull o2[4][4];
    float mrow[8], lrow[8];
    #pragma unroll
    for (int i2 = 0; i2 < 4; ++i2)
        #pragma unroll
        for (int j = 0; j < 4; ++j) o2[i2][j] = 0ull;
    #pragma unroll
    for (int i = 0; i < 8; ++i) { mrow[i] = NEGINF; lrow[i] = 0.0f; }

    const int ktmax = 2*qt + 1;
    for (int kt = 0; kt <= ktmax; ++kt) {
        __syncthreads();  // prev PV done (and Q load done on first iter)

        const float* Kg = g_K + (bh*S_LEN + kt*KCOLS)*HD;
        const float* Vg = g_V + (bh*S_LEN + kt*KCOLS)*HD;
        #pragma unroll
        for (int it = 0; it < 4; ++it) {
            int f = tid + it*256;       // < 1024
            int row = f >> 4, c4 = (f & 15) << 2;
            float4 kv = *(const float4*)(Kg + row*HD + c4);
            KTs[(c4+0)*KST + row] = kv.x;
            KTs[(c4+1)*KST + row] = kv.y;
            KTs[(c4+2)*KST + row] = kv.z;
            KTs[(c4+3)*KST + row] = kv.w;
            float4 vv = *(const float4*)(Vg + row*HD + c4);
            *(float4*)(Vs + row*VST + c4) = vv;
        }
        __syncthreads();

        // S = Q K^T  -> acc2[i2][j]: rows ty*8+2*i2+{lo,hi}, cols tx*4+j
        ull acc2[4][4];
        #pragma unroll
        for (int i2 = 0; i2 < 4; ++i2)
            #pragma unroll
            for (int j = 0; j < 4; ++j) acc2[i2][j] = 0ull;

        #pragma unroll 4
        for (int d = 0; d < HD; ++d) {
            const float* qrow = Qs + d*QST + ty*8;
            ull q0 = *(const ull*)(qrow + 0);
            ull q1 = *(const ull*)(qrow + 2);
            ull q2 = *(const ull*)(qrow + 4);
            ull q3 = *(const ull*)(qrow + 6);
            const float* krow = KTs + d*KST + tx*4;
            float2 ka = *(const float2*)(krow);
            float2 kb = *(const float2*)(krow + 2);
            ull k0 = dup2(ka.x), k1 = dup2(ka.y), k2 = dup2(kb.x), k3 = dup2(kb.y);
            fma2(acc2[0][0], q0, k0); fma2(acc2[0][1], q0, k1); fma2(acc2[0][2], q0, k2); fma2(acc2[0][3], q0, k3);
            fma2(acc2[1][0], q1, k0); fma2(acc2[1][1], q1, k1); fma2(acc2[1][2], q1, k2); fma2(acc2[1][3], q1, k3);
            fma2(acc2[2][0], q2, k0); fma2(acc2[2][1], q2, k1); fma2(acc2[2][2], q2, k2); fma2(acc2[2][3], q2, k3);
            fma2(acc2[3][0], q3, k0); fma2(acc2[3][1], q3, k1); fma2(acc2[3][2], q3, k2); fma2(acc2[3][3], q3, k3);
        }

        // softmax (per row-pair), repack exp'd P into acc2
        const bool boundary = (kt >= 2*qt);
        #pragma unroll
        for (int i2 = 0; i2 < 4; ++i2) {
            float flo[4], fhi[4];
            #pragma unroll
            for (int j = 0; j < 4; ++j) {
                float2 u = unpack2(acc2[i2][j]);
                flo[j] = u.x; fhi[j] = u.y;
            }
            if (boundary) {
                int rlo = qt*QROWS + ty*8 + 2*i2;
                int cb  = kt*KCOLS + tx*4;
                #pragma unroll
                for (int j = 0; j < 4; ++j) {
                    flo[j] = (cb + j > rlo)     ? NEGINF : flo[j]*0.125f;
                    fhi[j] = (cb + j > rlo + 1) ? NEGINF : fhi[j]*0.125f;
                }
            } else {
                #pragma unroll
                for (int j = 0; j < 4; ++j) { flo[j] *= 0.125f; fhi[j] *= 0.125f; }
            }

            float corrlo, corrhi;
            {   // row lo
                int i = 2*i2;
                float rm = fmaxf(fmaxf(flo[0], flo[1]), fmaxf(flo[2], flo[3]));
                #pragma unroll
                for (int off = 8; off > 0; off >>= 1)
                    rm = fmaxf(rm, __shfl_xor_sync(0xffffffffu, rm, off, 16));
                float mnew = fmaxf(mrow[i], rm);
                corrlo = __expf(mrow[i] - mnew);
                float rs = 0.0f;
                #pragma unroll
                for (int j = 0; j < 4; ++j) { flo[j] = __expf(flo[j] - mnew); rs += flo[j]; }
                #pragma unroll
                for (int off = 8; off > 0; off >>= 1)
                    rs += __shfl_xor_sync(0xffffffffu, rs, off, 16);
                lrow[i] = lrow[i]*corrlo + rs;
                mrow[i] = mnew;
            }
            {   // row hi
                int i = 2*i2 + 1;
                float rm = fmaxf(fmaxf(fhi[0], fhi[1]), fmaxf(fhi[2], fhi[3]));
                #pragma unroll
                for (int off = 8; off > 0; off >>= 1)
                    rm = fmaxf(rm, __shfl_xor_sync(0xffffffffu, rm, off, 16));
                float mnew = fmaxf(mrow[i], rm);
                corrhi = __expf(mrow[i] - mnew);
                float rs = 0.0f;
                #pragma unroll
                for (int j = 0; j < 4; ++j) { fhi[j] = __expf(fhi[j] - mnew); rs += fhi[j]; }
                #pragma unroll
                for (int off = 8; off > 0; off >>= 1)
                    rs += __shfl_xor_sync(0xffffffffu, rs, off, 16);
                lrow[i] = lrow[i]*corrhi + rs;
                mrow[i] = mnew;
            }
            ull c2 = pack2(corrlo, corrhi);
            #pragma unroll
            for (int j = 0; j < 4; ++j) {
                mul2(o2[i2][j], o2[i2][j], c2);
                acc2[i2][j] = pack2(flo[j], fhi[j]);
            }
        }

        // store P^T[k][r] as packed row-pairs (STS.64, 4-way worst case)
        #pragma unroll
        for (int j = 0; j < 4; ++j) {
            float* base = PTs + (tx*4 + j)*QST + ty*8;
            *(ull*)(base + 0) = acc2[0][j];
            *(ull*)(base + 2) = acc2[1][j];
            *(ull*)(base + 4) = acc2[2][j];
            *(ull*)(base + 6) = acc2[3][j];
        }
        __syncthreads();

        // O += P V
        #pragma unroll 4
        for (int k2 = 0; k2 < KCOLS; ++k2) {
            const float* prow = PTs + k2*QST + ty*8;
            ull p0 = *(const ull*)(prow + 0);
            ull p1 = *(const ull*)(prow + 2);
            ull p2 = *(const ull*)(prow + 4);
            ull p3 = *(const ull*)(prow + 6);
            float4 vv = *(const float4*)(Vs + k2*VST + tx*4);
            ull v0 = dup2(vv.x), v1 = dup2(vv.y), v2 = dup2(vv.z), v3 = dup2(vv.w);
            fma2(o2[0][0], p0, v0); fma2(o2[0][1], p0, v1); fma2(o2[0][2], p0, v2); fma2(o2[0][3], p0, v3);
            fma2(o2[1][0], p1, v0); fma2(o2[1][1], p1, v1); fma2(o2[1][2], p1, v2); fma2(o2[1][3], p1, v3);
            fma2(o2[2][0], p2, v0); fma2(o2[2][1], p2, v1); fma2(o2[2][2], p2, v2); fma2(o2[2][3], p2, v3);
            fma2(o2[3][0], p3, v0); fma2(o2[3][1], p3, v1); fma2(o2[3][2], p3, v2); fma2(o2[3][3], p3, v3);
        }
    }

    // epilogue: write [b, s, h*64+d]
    const int b = bh >> 4, h = bh & 15;
    #pragma unroll
    for (int i2 = 0; i2 < 4; ++i2) {
        float2 u0 = unpack2(o2[i2][0]);
        float2 u1 = unpack2(o2[i2][1]);
        float2 u2 = unpack2(o2[i2][2]);
        float2 u3 = unpack2(o2[i2][3]);
        int rlo = 2*i2, rhi = 2*i2 + 1;
        float invlo = 1.0f / lrow[rlo];
        float invhi = 1.0f / lrow[rhi];
        int sglo = qt*QROWS + ty*8 + rlo;
        int sghi = sglo + 1;
        *(float4*)(g_attn + (size_t)(b*S_LEN + sglo)*DMODEL + h*HD + tx*4) =
            make_float4(u0.x*invlo, u1.x*invlo, u2.x*invlo, u3.x*invlo);
        *(float4*)(g_attn + (size_t)(b*S_LEN + sghi)*DMODEL + h*HD + tx*4) =
            make_float4(u0.y*invhi, u1.y*invhi, u2.y*invhi, u3.y*invhi);
    }
}

// ---------------------------------------------------------------------------
extern "C" void kernel_launch(void* const* d_in, const int* in_sizes, int n_in,
                              void* d_out, int out_size) {
    const float* hs   = (const float*)d_in[0];   // hidden_states [2,2048,1024]
    const float* wqkv = (const float*)d_in[1];   // [1024,3072]
    const float* wout = (const float*)d_in[2];   // [1024,1024]
    const int*   pos  = (const int*)  d_in[3];   // pos_xyz (int32 or int64)
    float* out = (float*)d_out;

    const int n_pos = NTOK * 3;

    detect_pos64<<<1, 256>>>(pos, n_pos);
    convert_pos<<<(n_pos + 255)/256, 256>>>(pos, n_pos);
    build_tables<<<1, 1024>>>();

    // QKV projection + scatter
    sgemm_kernel<<<dim3(3*DMODEL/BN, NTOK/BM), 256>>>(
        hs, wqkv, nullptr, NTOK, 3*DMODEL, DMODEL, 1);

    // RoPE on Q, K
    rope_kernel<<<(NTOK*NPAIRS)/256, 256>>>();

    // Attention
    cudaFuncSetAttribute(attention_kernel,
                         cudaFuncAttributeMaxDynamicSharedMemorySize, ATT_SMEM);
    attention_kernel<<<dim3(S_LEN/QROWS, BATCH*NHEAD), 256, ATT_SMEM>>>();

    // Output projection (A = g_attn)
    sgemm_kernel<<<dim3(DMODEL/BN, NTOK/BM), 256>>>(
        hs, wout, out, NTOK, DMODEL, DMODEL, 2);
}

// round 10
// speedup vs baseline: 1.4389x; 1.3077x over previous
#include <cuda_runtime.h>
#include <cuda_bf16.h>
#include <math.h>
#include <stdint.h>

// Problem constants
#define BATCH   2
#define S_LEN   2048
#define NHEAD   16
#define HD      64
#define DMODEL  1024   // NHEAD*HD
#define NPAIRS  32     // HD/2
#define NTOK    (BATCH*S_LEN)   // 4096

typedef unsigned long long ull;

// Scratch (device globals — no allocation allowed).
// IMPORTANT: these are ONLY referenced from device code (mode flags select
// them inside kernels). Passing them as kernel args from host would bind the
// host shadow symbol (ATS-reachable on GB300 => silent wrong results).
__device__ float g_Q[BATCH*NHEAD*S_LEN*HD];
__device__ float g_K[BATCH*NHEAD*S_LEN*HD];
__device__ float g_V[BATCH*NHEAD*S_LEN*HD];
__device__ float g_attn[NTOK*DMODEL];
__device__ int   g_pos[NTOK*3];
__device__ int   g_is64;
__device__ float g_cos[NPAIRS*32];
__device__ float g_sin[NPAIRS*32];

// bf16 split operands for tensor-core GEMMs
__device__ __nv_bfloat16 g_hsHi[NTOK*DMODEL];
__device__ __nv_bfloat16 g_hsLo[NTOK*DMODEL];
__device__ __nv_bfloat16 g_aHi [NTOK*DMODEL];
__device__ __nv_bfloat16 g_aLo [NTOK*DMODEL];
__device__ __nv_bfloat16 g_wqkvT_hi[3*DMODEL*DMODEL];
__device__ __nv_bfloat16 g_wqkvT_lo[3*DMODEL*DMODEL];
__device__ __nv_bfloat16 g_woutT_hi[DMODEL*DMODEL];
__device__ __nv_bfloat16 g_woutT_lo[DMODEL*DMODEL];

#define NEGINF __int_as_float(0xff800000)

// ---------------------------------------------------------------------------
// packed f32x2 helpers (attention kernel)
// ---------------------------------------------------------------------------
__device__ __forceinline__ void fma2(ull &d, ull a, ull b) {
    asm("fma.rn.f32x2 %0, %1, %2, %0;" : "+l"(d) : "l"(a), "l"(b));
}
__device__ __forceinline__ void mul2(ull &d, ull a, ull b) {
    asm("mul.rn.f32x2 %0, %1, %2;" : "=l"(d) : "l"(a), "l"(b));
}
__device__ __forceinline__ ull pack2(float lo, float hi) {
    ull r;
    asm("mov.b64 %0, {%1, %2};" : "=l"(r) : "r"(__float_as_uint(lo)), "r"(__float_as_uint(hi)));
    return r;
}
__device__ __forceinline__ ull dup2(float x) {
    ull r;
    asm("mov.b64 %0, {%1, %1};" : "=l"(r) : "r"(__float_as_uint(x)));
    return r;
}
__device__ __forceinline__ float2 unpack2(ull v) {
    uint32_t lo, hi;
    asm("mov.b64 {%0, %1}, %2;" : "=r"(lo), "=r"(hi) : "l"(v));
    return make_float2(__uint_as_float(lo), __uint_as_float(hi));
}

// ---------------------------------------------------------------------------
// mma.sync m16n8k16 bf16 (arch-agnostic PTX, sm_80+ — compiles for compute_103)
// ---------------------------------------------------------------------------
__device__ __forceinline__ void mma16816(float* c, const uint32_t* a, const uint32_t* b) {
    asm volatile(
        "mma.sync.aligned.m16n8k16.row.col.f32.bf16.bf16.f32 "
        "{%0,%1,%2,%3}, {%4,%5,%6,%7}, {%8,%9}, {%0,%1,%2,%3};"
        : "+f"(c[0]), "+f"(c[1]), "+f"(c[2]), "+f"(c[3])
        : "r"(a[0]), "r"(a[1]), "r"(a[2]), "r"(a[3]), "r"(b[0]), "r"(b[1]));
}

// ---------------------------------------------------------------------------
// Position dtype detection + conversion
// ---------------------------------------------------------------------------
__global__ void detect_pos64(const int* __restrict__ raw, int n_words) {
    __shared__ int red[256];
    int acc = 0;
    for (int i = threadIdx.x; 2*i + 1 < n_words; i += 256)
        acc |= raw[2*i + 1];
    red[threadIdx.x] = acc;
    __syncthreads();
    for (int s1 = 128; s1 > 0; s1 >>= 1) {
        if (threadIdx.x < s1) red[threadIdx.x] |= red[threadIdx.x + s1];
        __syncthreads();
    }
    if (threadIdx.x == 0) g_is64 = (red[0] == 0) ? 1 : 0;
}

__global__ void convert_pos(const int* __restrict__ raw, int n) {
    int i = blockIdx.x * 256 + threadIdx.x;
    if (i >= n) return;
    int v = g_is64 ? raw[2*i] : raw[i];
    int ax = i % 3;
    int mx = (ax == 2) ? 7 : 31;
    v = v < 0 ? 0 : (v > mx ? mx : v);
    g_pos[i] = v;
}

__global__ void build_tables() {
    int t = threadIdx.x;            // 1024 threads
    int p = t >> 5, pos = t & 31;
    float inv;
    if (p < 10)      inv = powf(10000.0f, -(2.0f * p)        / 20.0f);
    else if (p < 20) inv = powf(10000.0f, -(2.0f * (p - 10)) / 20.0f);
    else             inv = powf(10000.0f, -(2.0f * (p - 20)) / 24.0f);
    float ang = (float)pos * inv;
    g_cos[t] = cosf(ang);
    g_sin[t] = sinf(ang);
}

// ---------------------------------------------------------------------------
// fp32 -> bf16 hi/lo split.  mode 0: src = ext (hidden_states) -> g_hs*.
//                            mode 1: src = g_attn              -> g_a*.
// ---------------------------------------------------------------------------
__global__ void split_fp32(const float* __restrict__ ext, int n, int mode) {
    int i = blockIdx.x * 256 + threadIdx.x;
    if (i >= n) return;
    const float* src = mode ? (const float*)g_attn : ext;
    __nv_bfloat16* hi = mode ? g_aHi : g_hsHi;
    __nv_bfloat16* lo = mode ? g_aLo : g_hsLo;
    float f = src[i];
    __nv_bfloat16 h = __float2bfloat16_rn(f);
    float r = f - __bfloat162float(h);
    hi[i] = h;
    lo[i] = __float2bfloat16_rn(r);
}

// ---------------------------------------------------------------------------
// Transpose W[K][N] -> T[N][K] with bf16 hi/lo split.
// which 0: -> g_wqkvT_*;  which 1: -> g_woutT_*.
// ---------------------------------------------------------------------------
__global__ void transpose_split(const float* __restrict__ W, int K, int N, int which) {
    __shared__ float tile[32][33];
    __nv_bfloat16* Thi = which ? g_woutT_hi : g_wqkvT_hi;
    __nv_bfloat16* Tlo = which ? g_woutT_lo : g_wqkvT_lo;
    int k0 = blockIdx.y * 32, n0 = blockIdx.x * 32;
    int x = threadIdx.x, y = threadIdx.y;
    #pragma unroll
    for (int i = y; i < 32; i += 8)
        tile[i][x] = W[(size_t)(k0 + i)*N + n0 + x];
    __syncthreads();
    #pragma unroll
    for (int i = y; i < 32; i += 8) {
        float f = tile[x][i];   // = W[k0+x][n0+i]
        __nv_bfloat16 h = __float2bfloat16_rn(f);
        float r = f - __bfloat162float(h);
        size_t o = (size_t)(n0 + i)*K + k0 + x;
        Thi[o] = h;
        Tlo[o] = __float2bfloat16_rn(r);
    }
}

// ---------------------------------------------------------------------------
// mma.sync bf16x3 GEMM.  C[M,N] = A[M,K] @ B^T  (B stored [N][K] K-major).
// CTA tile 128x128, BK=32, 256 threads = 8 warps (2m x 4n), warp tile 64x32.
// D = Ahi*Bhi + Ahi*Blo + Alo*Bhi  (fp32 accum; residual ~2^-16).
// mode 1: A=g_hs*, B=g_wqkvT_*, scatter into g_Q/g_K/g_V [b,h,s,d].
// mode 2: A=g_a*,  B=g_woutT_*, plain C write.
// ---------------------------------------------------------------------------
#define GK   1024
#define ASTR 40

__global__ __launch_bounds__(256)
void mma_gemm(float* __restrict__ C, int N_total, int mode)
{
    __shared__ __nv_bfloat16 sAhi[128*ASTR];
    __shared__ __nv_bfloat16 sAlo[128*ASTR];
    __shared__ __nv_bfloat16 sBhi[128*ASTR];
    __shared__ __nv_bfloat16 sBlo[128*ASTR];

    const __nv_bfloat16 *Ahi, *Alo, *Bhi, *Blo;
    if (mode == 1) { Ahi = g_hsHi; Alo = g_hsLo; Bhi = g_wqkvT_hi; Blo = g_wqkvT_lo; }
    else           { Ahi = g_aHi;  Alo = g_aLo;  Bhi = g_woutT_hi; Blo = g_woutT_lo; }

    const int tid  = threadIdx.x;
    const int lane = tid & 31;
    const int wid  = tid >> 5;
    const int warp_m = wid >> 2;        // 0..1 -> 64 rows
    const int warp_n = wid & 3;         // 0..3 -> 32 cols
    const int g = lane >> 2, t = lane & 3;
    const int m0 = blockIdx.y * 128;
    const int n0 = blockIdx.x * 128;

    float acc[4][4][4];
    #pragma unroll
    for (int mt = 0; mt < 4; ++mt)
        #pragma unroll
        for (int nt = 0; nt < 4; ++nt)
            #pragma unroll
            for (int q = 0; q < 4; ++q) acc[mt][nt][q] = 0.0f;

    for (int k0 = 0; k0 < GK; k0 += 32) {
        // Load chunk: 4 arrays x 128 rows x 32 bf16 = 2048 uint4 (8/thread)
        #pragma unroll
        for (int it = 0; it < 8; ++it) {
            int f = tid + it*256;
            int arr = f >> 9;            // 0:Ahi 1:Alo 2:Bhi 3:Blo
            int idx = f & 511;
            int row = idx >> 2, seg = idx & 3;
            const __nv_bfloat16* src =
                (arr == 0 ? Ahi : arr == 1 ? Alo : arr == 2 ? Bhi : Blo)
                + (size_t)((arr < 2 ? m0 : n0) + row)*GK + k0 + seg*8;
            __nv_bfloat16* dst =
                (arr == 0 ? sAhi : arr == 1 ? sAlo : arr == 2 ? sBhi : sBlo)
                + row*ASTR + seg*8;
            *(uint4*)dst = *(const uint4*)src;
        }
        __syncthreads();

        #pragma unroll
        for (int kk = 0; kk < 2; ++kk) {
            const int kof = kk*16 + 2*t;
            uint32_t ah[4][4], al[4][4], bh[4][2], bl[4][2];
            #pragma unroll
            for (int mt = 0; mt < 4; ++mt) {
                int r = warp_m*64 + mt*16 + g;
                const __nv_bfloat16* p0 = sAhi + r*ASTR + kof;
                ah[mt][0] = *(const uint32_t*)(p0);
                ah[mt][1] = *(const uint32_t*)(p0 + 8*ASTR);
                ah[mt][2] = *(const uint32_t*)(p0 + 8);
                ah[mt][3] = *(const uint32_t*)(p0 + 8*ASTR + 8);
                const __nv_bfloat16* p1 = sAlo + r*ASTR + kof;
                al[mt][0] = *(const uint32_t*)(p1);
                al[mt][1] = *(const uint32_t*)(p1 + 8*ASTR);
                al[mt][2] = *(const uint32_t*)(p1 + 8);
                al[mt][3] = *(const uint32_t*)(p1 + 8*ASTR + 8);
            }
            #pragma unroll
            for (int nt = 0; nt < 4; ++nt) {
                int r = warp_n*32 + nt*8 + g;
                const __nv_bfloat16* p0 = sBhi + r*ASTR + kof;
                bh[nt][0] = *(const uint32_t*)(p0);
                bh[nt][1] = *(const uint32_t*)(p0 + 8);
                const __nv_bfloat16* p1 = sBlo + r*ASTR + kof;
                bl[nt][0] = *(const uint32_t*)(p1);
                bl[nt][1] = *(const uint32_t*)(p1 + 8);
            }
            #pragma unroll
            for (int mt = 0; mt < 4; ++mt)
                #pragma unroll
                for (int nt = 0; nt < 4; ++nt) {
                    mma16816(acc[mt][nt], ah[mt], bh[nt]);
                    mma16816(acc[mt][nt], ah[mt], bl[nt]);
                    mma16816(acc[mt][nt], al[mt], bh[nt]);
                }
        }
        __syncthreads();
    }

    // Epilogue. Thread owns C[rows m0+warp_m*64+mt*16+{g,g+8}]
    //                     [cols n0+warp_n*32+nt*8+{2t,2t+1}]
    if (mode == 1) {
        #pragma unroll
        for (int mt = 0; mt < 4; ++mt) {
            #pragma unroll
            for (int half = 0; half < 2; ++half) {
                int m = m0 + warp_m*64 + mt*16 + g + half*8;
                int bb = m >> 11, s = m & 2047;
                #pragma unroll
                for (int nt = 0; nt < 4; ++nt) {
                    int n = n0 + warp_n*32 + nt*8 + 2*t;
                    int sec = n >> 10;
                    int r = n & 1023;
                    int h = r >> 6, d = r & 63;
                    float* dst = (sec == 0) ? g_Q : ((sec == 1) ? g_K : g_V);
                    float* p = dst + ((size_t)((bb*NHEAD + h)*S_LEN + s))*HD + d;
                    p[0] = acc[mt][nt][half*2 + 0];
                    p[1] = acc[mt][nt][half*2 + 1];
                }
            }
        }
    } else {
        #pragma unroll
        for (int mt = 0; mt < 4; ++mt) {
            #pragma unroll
            for (int half = 0; half < 2; ++half) {
                int m = m0 + warp_m*64 + mt*16 + g + half*8;
                float* rowp = C + (size_t)m*N_total + n0 + warp_n*32 + 2*t;
                #pragma unroll
                for (int nt = 0; nt < 4; ++nt)
                    *(float2*)(rowp + nt*8) =
                        make_float2(acc[mt][nt][half*2 + 0], acc[mt][nt][half*2 + 1]);
            }
        }
    }
}

// ---------------------------------------------------------------------------
// RoPE applied in-place to Q and K
// ---------------------------------------------------------------------------
__global__ void rope_kernel() {
    int idx = blockIdx.x * blockDim.x + threadIdx.x;
    int p = idx & 31;
    int t = idx >> 5;
    if (t >= BATCH * S_LEN) return;
    int b = t >> 11, s = t & 2047;
    int ax = (p < 10) ? 0 : ((p < 20) ? 1 : 2);
    int pos = g_pos[t*3 + ax];
    float c  = g_cos[p*32 + pos];
    float sn = g_sin[p*32 + pos];
    int base = ((b*NHEAD)*S_LEN + s)*HD + 2*p;
    #pragma unroll 4
    for (int h = 0; h < NHEAD; ++h) {
        int off = base + h * (S_LEN * HD);
        float2 q = *(float2*)(g_Q + off);
        float2 k = *(float2*)(g_K + off);
        float2 qo = make_float2(q.x*c - q.y*sn, q.y*c + q.x*sn);
        float2 ko = make_float2(k.x*c - k.y*sn, k.y*c + k.x*sn);
        *(float2*)(g_Q + off) = qo;
        *(float2*)(g_K + off) = ko;
    }
}

// ---------------------------------------------------------------------------
// Flash attention (causal), fp32 with FFMA2 — unchanged from R6 (proven).
// ---------------------------------------------------------------------------
#define QROWS 128
#define KCOLS 64
#define QST 130
#define KST 74
#define VST 72
#define ATT_SMEM ((64*QST + 64*KST + 64*QST + 64*VST) * 4)   // 103936 B

__global__ __launch_bounds__(256, 2)
void attention_kernel() {
    extern __shared__ float sm[];
    float* Qs  = sm;                    // [64][130] d-major (transposed Q)
    float* KTs = Qs  + 64*QST;          // [64][74]  d-major (transposed K)
    float* PTs = KTs + 64*KST;          // [64][130] k-major (transposed P)
    float* Vs  = PTs + 64*QST;          // [64][72]  natural V

    const int tid = threadIdx.x;
    const int tx = tid & 15, ty = tid >> 4;
    const int bh = blockIdx.y;
    const int qt = (int)gridDim.x - 1 - (int)blockIdx.x;  // big tiles first

    const float* Qg = g_Q + (bh*S_LEN + qt*QROWS)*HD;

    #pragma unroll
    for (int it = 0; it < 8; ++it) {
        int f = tid + it*256;           // < 2048
        int row = f >> 4, c4 = (f & 15) << 2;
        float4 v = *(const float4*)(Qg + row*HD + c4);
        Qs[(c4+0)*QST + row] = v.x;
        Qs[(c4+1)*QST + row] = v.y;
        Qs[(c4+2)*QST + row] = v.z;
        Qs[(c4+3)*QST + row] = v.w;
    }

    ull o2[4][4];
    float mrow[8], lrow[8];
    #pragma unroll
    for (int i2 = 0; i2 < 4; ++i2)
        #pragma unroll
        for (int j = 0; j < 4; ++j) o2[i2][j] = 0ull;
    #pragma unroll
    for (int i = 0; i < 8; ++i) { mrow[i] = NEGINF; lrow[i] = 0.0f; }

    const int ktmax = 2*qt + 1;
    for (int kt = 0; kt <= ktmax; ++kt) {
        __syncthreads();

        const float* Kg = g_K + (bh*S_LEN + kt*KCOLS)*HD;
        const float* Vg = g_V + (bh*S_LEN + kt*KCOLS)*HD;
        #pragma unroll
        for (int it = 0; it < 4; ++it) {
            int f = tid + it*256;       // < 1024
            int row = f >> 4, c4 = (f & 15) << 2;
            float4 kv = *(const float4*)(Kg + row*HD + c4);
            KTs[(c4+0)*KST + row] = kv.x;
            KTs[(c4+1)*KST + row] = kv.y;
            KTs[(c4+2)*KST + row] = kv.z;
            KTs[(c4+3)*KST + row] = kv.w;
            float4 vv = *(const float4*)(Vg + row*HD + c4);
            *(float4*)(Vs + row*VST + c4) = vv;
        }
        __syncthreads();

        ull acc2[4][4];
        #pragma unroll
        for (int i2 = 0; i2 < 4; ++i2)
            #pragma unroll
            for (int j = 0; j < 4; ++j) acc2[i2][j] = 0ull;

        #pragma unroll 4
        for (int d = 0; d < HD; ++d) {
            const float* qrow = Qs + d*QST + ty*8;
            ull q0 = *(const ull*)(qrow + 0);
            ull q1 = *(const ull*)(qrow + 2);
            ull q2 = *(const ull*)(qrow + 4);
            ull q3 = *(const ull*)(qrow + 6);
            const float* krow = KTs + d*KST + tx*4;
            float2 ka = *(const float2*)(krow);
            float2 kb = *(const float2*)(krow + 2);
            ull k0 = dup2(ka.x), k1 = dup2(ka.y), k2 = dup2(kb.x), k3 = dup2(kb.y);
            fma2(acc2[0][0], q0, k0); fma2(acc2[0][1], q0, k1); fma2(acc2[0][2], q0, k2); fma2(acc2[0][3], q0, k3);
            fma2(acc2[1][0], q1, k0); fma2(acc2[1][1], q1, k1); fma2(acc2[1][2], q1, k2); fma2(acc2[1][3], q1, k3);
            fma2(acc2[2][0], q2, k0); fma2(acc2[2][1], q2, k1); fma2(acc2[2][2], q2, k2); fma2(acc2[2][3], q2, k3);
            fma2(acc2[3][0], q3, k0); fma2(acc2[3][1], q3, k1); fma2(acc2[3][2], q3, k2); fma2(acc2[3][3], q3, k3);
        }

        const bool boundary = (kt >= 2*qt);
        #pragma unroll
        for (int i2 = 0; i2 < 4; ++i2) {
            float flo[4], fhi[4];
            #pragma unroll
            for (int j = 0; j < 4; ++j) {
                float2 u = unpack2(acc2[i2][j]);
                flo[j] = u.x; fhi[j] = u.y;
            }
            if (boundary) {
                int rlo = qt*QROWS + ty*8 + 2*i2;
                int cb  = kt*KCOLS + tx*4;
                #pragma unroll
                for (int j = 0; j < 4; ++j) {
                    flo[j] = (cb + j > rlo)     ? NEGINF : flo[j]*0.125f;
                    fhi[j] = (cb + j > rlo + 1) ? NEGINF : fhi[j]*0.125f;
                }
            } else {
                #pragma unroll
                for (int j = 0; j < 4; ++j) { flo[j] *= 0.125f; fhi[j] *= 0.125f; }
            }

            float corrlo, corrhi;
            {
                int i = 2*i2;
                float rm = fmaxf(fmaxf(flo[0], flo[1]), fmaxf(flo[2], flo[3]));
                #pragma unroll
                for (int off = 8; off > 0; off >>= 1)
                    rm = fmaxf(rm, __shfl_xor_sync(0xffffffffu, rm, off, 16));
                float mnew = fmaxf(mrow[i], rm);
                corrlo = __expf(mrow[i] - mnew);
                float rs = 0.0f;
                #pragma unroll
                for (int j = 0; j < 4; ++j) { flo[j] = __expf(flo[j] - mnew); rs += flo[j]; }
                #pragma unroll
                for (int off = 8; off > 0; off >>= 1)
                    rs += __shfl_xor_sync(0xffffffffu, rs, off, 16);
                lrow[i] = lrow[i]*corrlo + rs;
                mrow[i] = mnew;
            }
            {
                int i = 2*i2 + 1;
                float rm = fmaxf(fmaxf(fhi[0], fhi[1]), fmaxf(fhi[2], fhi[3]));
                #pragma unroll
                for (int off = 8; off > 0; off >>= 1)
                    rm = fmaxf(rm, __shfl_xor_sync(0xffffffffu, rm, off, 16));
                float mnew = fmaxf(mrow[i], rm);
                corrhi = __expf(mrow[i] - mnew);
                float rs = 0.0f;
                #pragma unroll
                for (int j = 0; j < 4; ++j) { fhi[j] = __expf(fhi[j] - mnew); rs += fhi[j]; }
                #pragma unroll
                for (int off = 8; off > 0; off >>= 1)
                    rs += __shfl_xor_sync(0xffffffffu, rs, off, 16);
                lrow[i] = lrow[i]*corrhi + rs;
                mrow[i] = mnew;
            }
            ull c2 = pack2(corrlo, corrhi);
            #pragma unroll
            for (int j = 0; j < 4; ++j) {
                mul2(o2[i2][j], o2[i2][j], c2);
                acc2[i2][j] = pack2(flo[j], fhi[j]);
            }
        }

        #pragma unroll
        for (int j = 0; j < 4; ++j) {
            float* base = PTs + (tx*4 + j)*QST + ty*8;
            *(ull*)(base + 0) = acc2[0][j];
            *(ull*)(base + 2) = acc2[1][j];
            *(ull*)(base + 4) = acc2[2][j];
            *(ull*)(base + 6) = acc2[3][j];
        }
        __syncthreads();

        #pragma unroll 4
        for (int k2 = 0; k2 < KCOLS; ++k2) {
            const float* prow = PTs + k2*QST + ty*8;
            ull p0 = *(const ull*)(prow + 0);
            ull p1 = *(const ull*)(prow + 2);
            ull p2 = *(const ull*)(prow + 4);
            ull p3 = *(const ull*)(prow + 6);
            float4 vv = *(const float4*)(Vs + k2*VST + tx*4);
            ull v0 = dup2(vv.x), v1 = dup2(vv.y), v2 = dup2(vv.z), v3 = dup2(vv.w);
            fma2(o2[0][0], p0, v0); fma2(o2[0][1], p0, v1); fma2(o2[0][2], p0, v2); fma2(o2[0][3], p0, v3);
            fma2(o2[1][0], p1, v0); fma2(o2[1][1], p1, v1); fma2(o2[1][2], p1, v2); fma2(o2[1][3], p1, v3);
            fma2(o2[2][0], p2, v0); fma2(o2[2][1], p2, v1); fma2(o2[2][2], p2, v2); fma2(o2[2][3], p2, v3);
            fma2(o2[3][0], p3, v0); fma2(o2[3][1], p3, v1); fma2(o2[3][2], p3, v2); fma2(o2[3][3], p3, v3);
        }
    }

    const int b = bh >> 4, h = bh & 15;
    #pragma unroll
    for (int i2 = 0; i2 < 4; ++i2) {
        float2 u0 = unpack2(o2[i2][0]);
        float2 u1 = unpack2(o2[i2][1]);
        float2 u2 = unpack2(o2[i2][2]);
        float2 u3 = unpack2(o2[i2][3]);
        int rlo = 2*i2, rhi = 2*i2 + 1;
        float invlo = 1.0f / lrow[rlo];
        float invhi = 1.0f / lrow[rhi];
        int sglo = qt*QROWS + ty*8 + rlo;
        int sghi = sglo + 1;
        *(float4*)(g_attn + (size_t)(b*S_LEN + sglo)*DMODEL + h*HD + tx*4) =
            make_float4(u0.x*invlo, u1.x*invlo, u2.x*invlo, u3.x*invlo);
        *(float4*)(g_attn + (size_t)(b*S_LEN + sghi)*DMODEL + h*HD + tx*4) =
            make_float4(u0.y*invhi, u1.y*invhi, u2.y*invhi, u3.y*invhi);
    }
}

// ---------------------------------------------------------------------------
extern "C" void kernel_launch(void* const* d_in, const int* in_sizes, int n_in,
                              void* d_out, int out_size) {
    const float* hs   = (const float*)d_in[0];   // [2,2048,1024]
    const float* wqkv = (const float*)d_in[1];   // [1024,3072]
    const float* wout = (const float*)d_in[2];   // [1024,1024]
    const int*   pos  = (const int*)  d_in[3];   // pos_xyz (int32 or int64)
    float* out = (float*)d_out;

    const int n_pos = NTOK * 3;

    detect_pos64<<<1, 256>>>(pos, n_pos);
    convert_pos<<<(n_pos + 255)/256, 256>>>(pos, n_pos);
    build_tables<<<1, 1024>>>();

    // Prepare bf16 split operands (device globals selected inside kernels)
    split_fp32<<<(NTOK*DMODEL)/256, 256>>>(hs, NTOK*DMODEL, 0);
    transpose_split<<<dim3(3*DMODEL/32, DMODEL/32), dim3(32, 8)>>>(wqkv, DMODEL, 3*DMODEL, 0);
    transpose_split<<<dim3(DMODEL/32, DMODEL/32), dim3(32, 8)>>>(wout, DMODEL, DMODEL, 1);

    // QKV projection (mma.sync tensor cores) + scatter
    mma_gemm<<<dim3(3*DMODEL/128, NTOK/128), 256>>>(nullptr, 3*DMODEL, 1);

    // RoPE on Q, K
    rope_kernel<<<(NTOK*NPAIRS)/256, 256>>>();

    // Attention
    cudaFuncSetAttribute(attention_kernel,
                         cudaFuncAttributeMaxDynamicSharedMemorySize, ATT_SMEM);
    attention_kernel<<<dim3(S_LEN/QROWS, BATCH*NHEAD), 256, ATT_SMEM>>>();

    // Output projection (mma.sync tensor cores)
    split_fp32<<<(NTOK*DMODEL)/256, 256>>>(nullptr, NTOK*DMODEL, 1);
    mma_gemm<<<dim3(DMODEL/128, NTOK/128), 256>>>(out, DMODEL, 2);
}

// round 11
// speedup vs baseline: 2.0497x; 1.4245x over previous
#include <cuda_runtime.h>
#include <cuda_bf16.h>
#include <math.h>
#include <stdint.h>

// Problem constants
#define BATCH   2
#define S_LEN   2048
#define NHEAD   16
#define HD      64
#define DMODEL  1024   // NHEAD*HD
#define NPAIRS  32     // HD/2
#define NTOK    (BATCH*S_LEN)   // 4096
#define NBH     (BATCH*NHEAD)   // 32

typedef unsigned long long ull;
typedef unsigned short u16;

// Scratch (device globals — no allocation allowed).
// IMPORTANT: only referenced from device code (host-shadow pitfall on GB300).
__device__ __align__(16) float g_Q[NBH*S_LEN*HD];      // fp32 pre-rope Q
__device__ __align__(16) float g_K[NBH*S_LEN*HD];      // fp32 pre-rope K
__device__ __align__(16) float g_attn[NTOK*DMODEL];
__device__ int   g_pos[NTOK*3];
__device__ int   g_is64;
__device__ float g_cos[NPAIRS*32];
__device__ float g_sin[NPAIRS*32];

// bf16 hi/lo split operands (stored as raw u16 bits)
__device__ __align__(16) u16 g_Qhi[NBH*S_LEN*HD];
__device__ __align__(16) u16 g_Qlo[NBH*S_LEN*HD];
__device__ __align__(16) u16 g_Khi[NBH*S_LEN*HD];
__device__ __align__(16) u16 g_Klo[NBH*S_LEN*HD];
__device__ __align__(16) u16 g_Vhi[NBH*S_LEN*HD];
__device__ __align__(16) u16 g_Vlo[NBH*S_LEN*HD];

__device__ __align__(16) __nv_bfloat16 g_hsHi[NTOK*DMODEL];
__device__ __align__(16) __nv_bfloat16 g_hsLo[NTOK*DMODEL];
__device__ __align__(16) __nv_bfloat16 g_aHi [NTOK*DMODEL];
__device__ __align__(16) __nv_bfloat16 g_aLo [NTOK*DMODEL];
__device__ __align__(16) __nv_bfloat16 g_wqkvT_hi[3*DMODEL*DMODEL];
__device__ __align__(16) __nv_bfloat16 g_wqkvT_lo[3*DMODEL*DMODEL];
__device__ __align__(16) __nv_bfloat16 g_woutT_hi[DMODEL*DMODEL];
__device__ __align__(16) __nv_bfloat16 g_woutT_lo[DMODEL*DMODEL];

#define NEGINF __int_as_float(0xff800000)

// ---------------------------------------------------------------------------
// helpers
// ---------------------------------------------------------------------------
// packed bf16x2: element0 (low half) = lo_elem, element1 (high half) = hi_elem
__device__ __forceinline__ uint32_t cvt_bf16x2(float hi_elem, float lo_elem) {
    uint32_t r;
    asm("cvt.rn.bf16x2.f32 %0, %1, %2;" : "=r"(r) : "f"(hi_elem), "f"(lo_elem));
    return r;
}

// mma.sync m16n8k16 bf16 (arch-agnostic PTX, sm_80+)
__device__ __forceinline__ void mma16816(float* c, const uint32_t* a, const uint32_t* b) {
    asm volatile(
        "mma.sync.aligned.m16n8k16.row.col.f32.bf16.bf16.f32 "
        "{%0,%1,%2,%3}, {%4,%5,%6,%7}, {%8,%9}, {%0,%1,%2,%3};"
        : "+f"(c[0]), "+f"(c[1]), "+f"(c[2]), "+f"(c[3])
        : "r"(a[0]), "r"(a[1]), "r"(a[2]), "r"(a[3]), "r"(b[0]), "r"(b[1]));
}

// ---------------------------------------------------------------------------
// Position dtype detection + conversion
// ---------------------------------------------------------------------------
__global__ void detect_pos64(const int* __restrict__ raw, int n_words) {
    __shared__ int red[256];
    int acc = 0;
    for (int i = threadIdx.x; 2*i + 1 < n_words; i += 256)
        acc |= raw[2*i + 1];
    red[threadIdx.x] = acc;
    __syncthreads();
    for (int s1 = 128; s1 > 0; s1 >>= 1) {
        if (threadIdx.x < s1) red[threadIdx.x] |= red[threadIdx.x + s1];
        __syncthreads();
    }
    if (threadIdx.x == 0) g_is64 = (red[0] == 0) ? 1 : 0;
}

__global__ void convert_pos(const int* __restrict__ raw, int n) {
    int i = blockIdx.x * 256 + threadIdx.x;
    if (i >= n) return;
    int v = g_is64 ? raw[2*i] : raw[i];
    int ax = i % 3;
    int mx = (ax == 2) ? 7 : 31;
    v = v < 0 ? 0 : (v > mx ? mx : v);
    g_pos[i] = v;
}

__global__ void build_tables() {
    int t = threadIdx.x;            // 1024 threads
    int p = t >> 5, pos = t & 31;
    float inv;
    if (p < 10)      inv = powf(10000.0f, -(2.0f * p)        / 20.0f);
    else if (p < 20) inv = powf(10000.0f, -(2.0f * (p - 10)) / 20.0f);
    else             inv = powf(10000.0f, -(2.0f * (p - 20)) / 24.0f);
    float ang = (float)pos * inv;
    g_cos[t] = cosf(ang);
    g_sin[t] = sinf(ang);
}

// ---------------------------------------------------------------------------
// fp32 -> bf16 hi/lo split.  mode 0: src = ext -> g_hs*;  mode 1: g_attn -> g_a*.
// ---------------------------------------------------------------------------
__global__ void split_fp32(const float* __restrict__ ext, int n, int mode) {
    int i = blockIdx.x * 256 + threadIdx.x;
    if (i >= n) return;
    const float* src = mode ? (const float*)g_attn : ext;
    __nv_bfloat16* hi = mode ? g_aHi : g_hsHi;
    __nv_bfloat16* lo = mode ? g_aLo : g_hsLo;
    float f = src[i];
    __nv_bfloat16 h = __float2bfloat16_rn(f);
    float r = f - __bfloat162float(h);
    hi[i] = h;
    lo[i] = __float2bfloat16_rn(r);
}

// ---------------------------------------------------------------------------
// Transpose W[K][N] -> T[N][K] with bf16 hi/lo split.
// ---------------------------------------------------------------------------
__global__ void transpose_split(const float* __restrict__ W, int K, int N, int which) {
    __shared__ float tile[32][33];
    __nv_bfloat16* Thi = which ? g_woutT_hi : g_wqkvT_hi;
    __nv_bfloat16* Tlo = which ? g_woutT_lo : g_wqkvT_lo;
    int k0 = blockIdx.y * 32, n0 = blockIdx.x * 32;
    int x = threadIdx.x, y = threadIdx.y;
    #pragma unroll
    for (int i = y; i < 32; i += 8)
        tile[i][x] = W[(size_t)(k0 + i)*N + n0 + x];
    __syncthreads();
    #pragma unroll
    for (int i = y; i < 32; i += 8) {
        float f = tile[x][i];
        __nv_bfloat16 h = __float2bfloat16_rn(f);
        float r = f - __bfloat162float(h);
        size_t o = (size_t)(n0 + i)*K + k0 + x;
        Thi[o] = h;
        Tlo[o] = __float2bfloat16_rn(r);
    }
}

// ---------------------------------------------------------------------------
// mma.sync bf16x3 GEMM (as R10).  mode 1: scatter Q,K fp32 + V bf16 hi/lo.
// mode 2: plain C write.
// ---------------------------------------------------------------------------
#define GK   1024
#define ASTR 40

__global__ __launch_bounds__(256)
void mma_gemm(float* __restrict__ C, int N_total, int mode)
{
    __shared__ __nv_bfloat16 sAhi[128*ASTR];
    __shared__ __nv_bfloat16 sAlo[128*ASTR];
    __shared__ __nv_bfloat16 sBhi[128*ASTR];
    __shared__ __nv_bfloat16 sBlo[128*ASTR];

    const __nv_bfloat16 *Ahi, *Alo, *Bhi, *Blo;
    if (mode == 1) { Ahi = g_hsHi; Alo = g_hsLo; Bhi = g_wqkvT_hi; Blo = g_wqkvT_lo; }
    else           { Ahi = g_aHi;  Alo = g_aLo;  Bhi = g_woutT_hi; Blo = g_woutT_lo; }

    const int tid  = threadIdx.x;
    const int lane = tid & 31;
    const int wid  = tid >> 5;
    const int warp_m = wid >> 2;
    const int warp_n = wid & 3;
    const int g = lane >> 2, t = lane & 3;
    const int m0 = blockIdx.y * 128;
    const int n0 = blockIdx.x * 128;

    float acc[4][4][4];
    #pragma unroll
    for (int mt = 0; mt < 4; ++mt)
        #pragma unroll
        for (int nt = 0; nt < 4; ++nt)
            #pragma unroll
            for (int q = 0; q < 4; ++q) acc[mt][nt][q] = 0.0f;

    for (int k0 = 0; k0 < GK; k0 += 32) {
        #pragma unroll
        for (int it = 0; it < 8; ++it) {
            int f = tid + it*256;
            int arr = f >> 9;
            int idx = f & 511;
            int row = idx >> 2, seg = idx & 3;
            const __nv_bfloat16* src =
                (arr == 0 ? Ahi : arr == 1 ? Alo : arr == 2 ? Bhi : Blo)
                + (size_t)((arr < 2 ? m0 : n0) + row)*GK + k0 + seg*8;
            __nv_bfloat16* dst =
                (arr == 0 ? sAhi : arr == 1 ? sAlo : arr == 2 ? sBhi : sBlo)
                + row*ASTR + seg*8;
            *(uint4*)dst = *(const uint4*)src;
        }
        __syncthreads();

        #pragma unroll
        for (int kk = 0; kk < 2; ++kk) {
            const int kof = kk*16 + 2*t;
            uint32_t ah[4][4], al[4][4], bh[4][2], bl[4][2];
            #pragma unroll
            for (int mt = 0; mt < 4; ++mt) {
                int r = warp_m*64 + mt*16 + g;
                const __nv_bfloat16* p0 = sAhi + r*ASTR + kof;
                ah[mt][0] = *(const uint32_t*)(p0);
                ah[mt][1] = *(const uint32_t*)(p0 + 8*ASTR);
                ah[mt][2] = *(const uint32_t*)(p0 + 8);
                ah[mt][3] = *(const uint32_t*)(p0 + 8*ASTR + 8);
                const __nv_bfloat16* p1 = sAlo + r*ASTR + kof;
                al[mt][0] = *(const uint32_t*)(p1);
                al[mt][1] = *(const uint32_t*)(p1 + 8*ASTR);
                al[mt][2] = *(const uint32_t*)(p1 + 8);
                al[mt][3] = *(const uint32_t*)(p1 + 8*ASTR + 8);
            }
            #pragma unroll
            for (int nt = 0; nt < 4; ++nt) {
                int r = warp_n*32 + nt*8 + g;
                const __nv_bfloat16* p0 = sBhi + r*ASTR + kof;
                bh[nt][0] = *(const uint32_t*)(p0);
                bh[nt][1] = *(const uint32_t*)(p0 + 8);
                const __nv_bfloat16* p1 = sBlo + r*ASTR + kof;
                bl[nt][0] = *(const uint32_t*)(p1);
                bl[nt][1] = *(const uint32_t*)(p1 + 8);
            }
            #pragma unroll
            for (int mt = 0; mt < 4; ++mt)
                #pragma unroll
                for (int nt = 0; nt < 4; ++nt) {
                    mma16816(acc[mt][nt], ah[mt], bh[nt]);
                    mma16816(acc[mt][nt], ah[mt], bl[nt]);
                    mma16816(acc[mt][nt], al[mt], bh[nt]);
                }
        }
        __syncthreads();
    }

    if (mode == 1) {
        #pragma unroll
        for (int mt = 0; mt < 4; ++mt) {
            #pragma unroll
            for (int half = 0; half < 2; ++half) {
                int m = m0 + warp_m*64 + mt*16 + g + half*8;
                int bb = m >> 11, s = m & 2047;
                #pragma unroll
                for (int nt = 0; nt < 4; ++nt) {
                    int n = n0 + warp_n*32 + nt*8 + 2*t;
                    int sec = n >> 10;
                    int r = n & 1023;
                    int h = r >> 6, d = r & 63;
                    size_t idx = ((size_t)((bb*NHEAD + h)*S_LEN + s))*HD + d;
                    float x0 = acc[mt][nt][half*2 + 0];
                    float x1 = acc[mt][nt][half*2 + 1];
                    if (sec == 0) { g_Q[idx] = x0; g_Q[idx+1] = x1; }
                    else if (sec == 1) { g_K[idx] = x0; g_K[idx+1] = x1; }
                    else {
                        uint32_t hv = cvt_bf16x2(x1, x0);
                        float h0 = __uint_as_float(hv << 16);
                        float h1 = __uint_as_float(hv & 0xffff0000u);
                        uint32_t lv = cvt_bf16x2(x1 - h1, x0 - h0);
                        *(uint32_t*)(g_Vhi + idx) = hv;
                        *(uint32_t*)(g_Vlo + idx) = lv;
                    }
                }
            }
        }
    } else {
        #pragma unroll
        for (int mt = 0; mt < 4; ++mt) {
            #pragma unroll
            for (int half = 0; half < 2; ++half) {
                int m = m0 + warp_m*64 + mt*16 + g + half*8;
                float* rowp = C + (size_t)m*N_total + n0 + warp_n*32 + 2*t;
                #pragma unroll
                for (int nt = 0; nt < 4; ++nt)
                    *(float2*)(rowp + nt*8) =
                        make_float2(acc[mt][nt][half*2 + 0], acc[mt][nt][half*2 + 1]);
            }
        }
    }
}

// ---------------------------------------------------------------------------
// RoPE: read fp32 Q/K, rotate, emit bf16 hi/lo splits.
// ---------------------------------------------------------------------------
__global__ void rope_kernel() {
    int idx = blockIdx.x * blockDim.x + threadIdx.x;
    int p = idx & 31;
    int t = idx >> 5;
    if (t >= NTOK) return;
    int b = t >> 11, s = t & 2047;
    int ax = (p < 10) ? 0 : ((p < 20) ? 1 : 2);
    int pos = g_pos[t*3 + ax];
    float c  = g_cos[p*32 + pos];
    float sn = g_sin[p*32 + pos];
    int base = ((b*NHEAD)*S_LEN + s)*HD + 2*p;
    #pragma unroll 4
    for (int h = 0; h < NHEAD; ++h) {
        int off = base + h * (S_LEN * HD);
        float2 q = *(float2*)(g_Q + off);
        float2 k = *(float2*)(g_K + off);
        float2 qo = make_float2(q.x*c - q.y*sn, q.y*c + q.x*sn);
        float2 ko = make_float2(k.x*c - k.y*sn, k.y*c + k.x*sn);
        uint32_t qh = cvt_bf16x2(qo.y, qo.x);
        float qh0 = __uint_as_float(qh << 16), qh1 = __uint_as_float(qh & 0xffff0000u);
        uint32_t ql = cvt_bf16x2(qo.y - qh1, qo.x - qh0);
        uint32_t kh = cvt_bf16x2(ko.y, ko.x);
        float kh0 = __uint_as_float(kh << 16), kh1 = __uint_as_float(kh & 0xffff0000u);
        uint32_t kl = cvt_bf16x2(ko.y - kh1, ko.x - kh0);
        *(uint32_t*)(g_Qhi + off) = qh;
        *(uint32_t*)(g_Qlo + off) = ql;
        *(uint32_t*)(g_Khi + off) = kh;
        *(uint32_t*)(g_Klo + off) = kl;
    }
}

// ---------------------------------------------------------------------------
// Flash attention (causal) on mma.sync tensor cores, bf16x3 splits.
// CTA: 128 q-rows x 64 k-cols, 8 warps x 16 rows each, full 64 cols per warp.
// Smem (u16, stride 72): Qhi/Qlo[128][72], Khi/Klo[64][72],
//                        VThi/VTlo[64(d)][72(key)].
// S accums repack in-register into PV A-fragments (hi + lo split of P).
// ---------------------------------------------------------------------------
#define AS2 72
#define ATT_SMEM ((128*AS2*2 + 64*AS2*4) * 2)   // 73728 B

__global__ __launch_bounds__(256, 2)
void attention_mma() {
    extern __shared__ u16 sb[];
    u16* sQh = sb;                  // [128][72]
    u16* sQl = sQh + 128*AS2;
    u16* sKh = sQl + 128*AS2;       // [64][72]
    u16* sKl = sKh + 64*AS2;
    u16* sVh = sKl + 64*AS2;        // V^T: [d][key]
    u16* sVl = sVh + 64*AS2;

    const int tid  = threadIdx.x;
    const int lane = tid & 31;
    const int wid  = tid >> 5;      // 0..7
    const int g = lane >> 2, t = lane & 3;
    const int bh = blockIdx.y;
    const int qt = (int)gridDim.x - 1 - (int)blockIdx.x;   // big tiles first

    const size_t hb = (size_t)bh * S_LEN;

    // Load Q tile (128x64 hi/lo)
    {
        const u16* Qh = g_Qhi + (hb + qt*128)*HD;
        const u16* Ql = g_Qlo + (hb + qt*128)*HD;
        #pragma unroll
        for (int it = 0; it < 4; ++it) {
            int f = tid + it*256;           // < 1024
            int row = f >> 3, seg = f & 7;
            *(uint4*)(sQh + row*AS2 + seg*8) = *(const uint4*)(Qh + row*HD + seg*8);
            *(uint4*)(sQl + row*AS2 + seg*8) = *(const uint4*)(Ql + row*HD + seg*8);
        }
    }

    float o[8][4];
    #pragma unroll
    for (int nt = 0; nt < 8; ++nt)
        #pragma unroll
        for (int q = 0; q < 4; ++q) o[nt][q] = 0.0f;
    float m0 = NEGINF, m1 = NEGINF, l0 = 0.0f, l1 = 0.0f;

    const int rowg = qt*128 + wid*16 + g;

    for (int kt = 0; kt <= 2*qt + 1; ++kt) {
        __syncthreads();
        // K tile (natural) + V tile (transposed)
        {
            const u16* Kh = g_Khi + (hb + kt*64)*HD;
            const u16* Kl = g_Klo + (hb + kt*64)*HD;
            #pragma unroll
            for (int it = 0; it < 2; ++it) {
                int f = tid + it*256;       // < 512
                int row = f >> 3, seg = f & 7;
                *(uint4*)(sKh + row*AS2 + seg*8) = *(const uint4*)(Kh + row*HD + seg*8);
                *(uint4*)(sKl + row*AS2 + seg*8) = *(const uint4*)(Kl + row*HD + seg*8);
            }
            const u16* Vh = g_Vhi + (hb + kt*64)*HD;
            const u16* Vl = g_Vlo + (hb + kt*64)*HD;
            #pragma unroll
            for (int it = 0; it < 2; ++it) {
                int f = tid + it*256;       // < 512
                int key = f & 63, dseg = f >> 6;   // dseg 0..7
                uint4 vh = *(const uint4*)(Vh + (key)*HD + dseg*8 + 0);
                uint4 vl = *(const uint4*)(Vl + (key)*HD + dseg*8 + 0);
                const u16* eh = (const u16*)&vh;
                const u16* el = (const u16*)&vl;
                #pragma unroll
                for (int j = 0; j < 8; ++j) {
                    sVh[(dseg*8 + j)*AS2 + key] = eh[j];
                    sVl[(dseg*8 + j)*AS2 + key] = el[j];
                }
            }
        }
        __syncthreads();

        // ---- S = Q K^T (3-term bf16x3) ----
        float c[8][4];
        #pragma unroll
        for (int nt = 0; nt < 8; ++nt)
            #pragma unroll
            for (int q = 0; q < 4; ++q) c[nt][q] = 0.0f;

        #pragma unroll
        for (int kc = 0; kc < 4; ++kc) {
            const int ar = wid*16 + g;
            const int ko = kc*16 + 2*t;
            uint32_t ah[4], al[4];
            ah[0] = *(const uint32_t*)(sQh + ar*AS2 + ko);
            ah[1] = *(const uint32_t*)(sQh + (ar+8)*AS2 + ko);
            ah[2] = *(const uint32_t*)(sQh + ar*AS2 + ko + 8);
            ah[3] = *(const uint32_t*)(sQh + (ar+8)*AS2 + ko + 8);
            al[0] = *(const uint32_t*)(sQl + ar*AS2 + ko);
            al[1] = *(const uint32_t*)(sQl + (ar+8)*AS2 + ko);
            al[2] = *(const uint32_t*)(sQl + ar*AS2 + ko + 8);
            al[3] = *(const uint32_t*)(sQl + (ar+8)*AS2 + ko + 8);
            #pragma unroll
            for (int nt = 0; nt < 8; ++nt) {
                const int br = nt*8 + g;
                uint32_t bh2[2], bl2[2];
                bh2[0] = *(const uint32_t*)(sKh + br*AS2 + ko);
                bh2[1] = *(const uint32_t*)(sKh + br*AS2 + ko + 8);
                bl2[0] = *(const uint32_t*)(sKl + br*AS2 + ko);
                bl2[1] = *(const uint32_t*)(sKl + br*AS2 + ko + 8);
                mma16816(c[nt], ah, bh2);
                mma16816(c[nt], ah, bl2);
                mma16816(c[nt], al, bh2);
            }
        }

        // ---- mask + scale ----
        if (kt >= 2*qt) {
            #pragma unroll
            for (int nt = 0; nt < 8; ++nt) {
                int col = kt*64 + nt*8 + 2*t;
                c[nt][0] = (col     > rowg    ) ? NEGINF : c[nt][0]*0.125f;
                c[nt][1] = (col + 1 > rowg    ) ? NEGINF : c[nt][1]*0.125f;
                c[nt][2] = (col     > rowg + 8) ? NEGINF : c[nt][2]*0.125f;
                c[nt][3] = (col + 1 > rowg + 8) ? NEGINF : c[nt][3]*0.125f;
            }
        } else {
            #pragma unroll
            for (int nt = 0; nt < 8; ++nt) {
                c[nt][0] *= 0.125f; c[nt][1] *= 0.125f;
                c[nt][2] *= 0.125f; c[nt][3] *= 0.125f;
            }
        }

        // ---- online softmax (rows g and g+8; reduce over 4 t-lanes) ----
        float rmax0 = NEGINF, rmax1 = NEGINF;
        #pragma unroll
        for (int nt = 0; nt < 8; ++nt) {
            rmax0 = fmaxf(rmax0, fmaxf(c[nt][0], c[nt][1]));
            rmax1 = fmaxf(rmax1, fmaxf(c[nt][2], c[nt][3]));
        }
        rmax0 = fmaxf(rmax0, __shfl_xor_sync(0xffffffffu, rmax0, 1));
        rmax0 = fmaxf(rmax0, __shfl_xor_sync(0xffffffffu, rmax0, 2));
        rmax1 = fmaxf(rmax1, __shfl_xor_sync(0xffffffffu, rmax1, 1));
        rmax1 = fmaxf(rmax1, __shfl_xor_sync(0xffffffffu, rmax1, 2));
        float mn0 = fmaxf(m0, rmax0), mn1 = fmaxf(m1, rmax1);
        float corr0 = __expf(m0 - mn0), corr1 = __expf(m1 - mn1);
        float rs0 = 0.0f, rs1 = 0.0f;
        #pragma unroll
        for (int nt = 0; nt < 8; ++nt) {
            c[nt][0] = __expf(c[nt][0] - mn0);
            c[nt][1] = __expf(c[nt][1] - mn0);
            c[nt][2] = __expf(c[nt][2] - mn1);
            c[nt][3] = __expf(c[nt][3] - mn1);
            rs0 += c[nt][0] + c[nt][1];
            rs1 += c[nt][2] + c[nt][3];
        }
        rs0 += __shfl_xor_sync(0xffffffffu, rs0, 1);
        rs0 += __shfl_xor_sync(0xffffffffu, rs0, 2);
        rs1 += __shfl_xor_sync(0xffffffffu, rs1, 1);
        rs1 += __shfl_xor_sync(0xffffffffu, rs1, 2);
        l0 = l0*corr0 + rs0;  m0 = mn0;
        l1 = l1*corr1 + rs1;  m1 = mn1;
        #pragma unroll
        for (int nt = 0; nt < 8; ++nt) {
            o[nt][0] *= corr0; o[nt][1] *= corr0;
            o[nt][2] *= corr1; o[nt][3] *= corr1;
        }

        // ---- O += P V (P repacked in-register, hi/lo split) ----
        #pragma unroll
        for (int kc = 0; kc < 4; ++kc) {
            const int j0 = 2*kc, j1 = 2*kc + 1;
            uint32_t ah[4], al[4];
            {
                uint32_t h0 = cvt_bf16x2(c[j0][1], c[j0][0]);
                uint32_t h1 = cvt_bf16x2(c[j0][3], c[j0][2]);
                uint32_t h2 = cvt_bf16x2(c[j1][1], c[j1][0]);
                uint32_t h3 = cvt_bf16x2(c[j1][3], c[j1][2]);
                ah[0] = h0; ah[1] = h1; ah[2] = h2; ah[3] = h3;
                al[0] = cvt_bf16x2(c[j0][1] - __uint_as_float(h0 & 0xffff0000u),
                                   c[j0][0] - __uint_as_float(h0 << 16));
                al[1] = cvt_bf16x2(c[j0][3] - __uint_as_float(h1 & 0xffff0000u),
                                   c[j0][2] - __uint_as_float(h1 << 16));
                al[2] = cvt_bf16x2(c[j1][1] - __uint_as_float(h2 & 0xffff0000u),
                                   c[j1][0] - __uint_as_float(h2 << 16));
                al[3] = cvt_bf16x2(c[j1][3] - __uint_as_float(h3 & 0xffff0000u),
                                   c[j1][2] - __uint_as_float(h3 << 16));
            }
            const int ko = kc*16 + 2*t;
            #pragma unroll
            for (int nt = 0; nt < 8; ++nt) {
                const int br = nt*8 + g;       // d index
                uint32_t bh2[2], bl2[2];
                bh2[0] = *(const uint32_t*)(sVh + br*AS2 + ko);
                bh2[1] = *(const uint32_t*)(sVh + br*AS2 + ko + 8);
                bl2[0] = *(const uint32_t*)(sVl + br*AS2 + ko);
                bl2[1] = *(const uint32_t*)(sVl + br*AS2 + ko + 8);
                mma16816(o[nt], ah, bh2);
                mma16816(o[nt], ah, bl2);
                mma16816(o[nt], al, bh2);
            }
        }
    }

    // ---- epilogue: write [b, s, h*64+d] ----
    const int b = bh >> 4, h = bh & 15;
    const float inv0 = 1.0f / l0, inv1 = 1.0f / l1;
    const int sg0 = qt*128 + wid*16 + g;
    #pragma unroll
    for (int nt = 0; nt < 8; ++nt) {
        int col = h*HD + nt*8 + 2*t;
        *(float2*)(g_attn + (size_t)(b*S_LEN + sg0)*DMODEL + col) =
            make_float2(o[nt][0]*inv0, o[nt][1]*inv0);
        *(float2*)(g_attn + (size_t)(b*S_LEN + sg0 + 8)*DMODEL + col) =
            make_float2(o[nt][2]*inv1, o[nt][3]*inv1);
    }
}

// ---------------------------------------------------------------------------
extern "C" void kernel_launch(void* const* d_in, const int* in_sizes, int n_in,
                              void* d_out, int out_size) {
    const float* hs   = (const float*)d_in[0];   // [2,2048,1024]
    const float* wqkv = (const float*)d_in[1];   // [1024,3072]
    const float* wout = (const float*)d_in[2];   // [1024,1024]
    const int*   pos  = (const int*)  d_in[3];   // pos_xyz (int32 or int64)
    float* out = (float*)d_out;

    const int n_pos = NTOK * 3;

    detect_pos64<<<1, 256>>>(pos, n_pos);
    convert_pos<<<(n_pos + 255)/256, 256>>>(pos, n_pos);
    build_tables<<<1, 1024>>>();

    // Prepare bf16 split operands (device globals selected inside kernels)
    split_fp32<<<(NTOK*DMODEL)/256, 256>>>(hs, NTOK*DMODEL, 0);
    transpose_split<<<dim3(3*DMODEL/32, DMODEL/32), dim3(32, 8)>>>(wqkv, DMODEL, 3*DMODEL, 0);
    transpose_split<<<dim3(DMODEL/32, DMODEL/32), dim3(32, 8)>>>(wout, DMODEL, DMODEL, 1);

    // QKV projection + scatter (Q,K fp32; V bf16 hi/lo)
    mma_gemm<<<dim3(3*DMODEL/128, NTOK/128), 256>>>(nullptr, 3*DMODEL, 1);

    // RoPE -> bf16 hi/lo Q,K
    rope_kernel<<<(NTOK*NPAIRS)/256, 256>>>();

    // Attention (tensor cores)
    cudaFuncSetAttribute(attention_mma,
                         cudaFuncAttributeMaxDynamicSharedMemorySize, ATT_SMEM);
    attention_mma<<<dim3(S_LEN/128, NBH), 256, ATT_SMEM>>>();

    // Output projection
    split_fp32<<<(NTOK*DMODEL)/256, 256>>>(nullptr, NTOK*DMODEL, 1);
    mma_gemm<<<dim3(DMODEL/128, NTOK/128), 256>>>(out, DMODEL, 2);
}

// round 12
// speedup vs baseline: 2.5497x; 1.2439x over previous
#include <cuda_runtime.h>
#include <cuda_bf16.h>
#include <math.h>
#include <stdint.h>

// Problem constants
#define BATCH   2
#define S_LEN   2048
#define NHEAD   16
#define HD      64
#define DMODEL  1024   // NHEAD*HD
#define NPAIRS  32     // HD/2
#define NTOK    (BATCH*S_LEN)   // 4096
#define NBH     (BATCH*NHEAD)   // 32

typedef unsigned long long ull;
typedef unsigned short u16;

// Scratch (device globals — no allocation allowed).
// Only referenced from device code (GB300 host-shadow/ATS pitfall).
__device__ __align__(16) float g_attn[NTOK*DMODEL];
__device__ int   g_pos[NTOK*3];
__device__ int   g_is64;
__device__ float g_cos[NPAIRS*32];
__device__ float g_sin[NPAIRS*32];

// bf16 hi/lo split operands (raw u16 bits)
__device__ __align__(16) u16 g_Qhi[NBH*S_LEN*HD];
__device__ __align__(16) u16 g_Qlo[NBH*S_LEN*HD];
__device__ __align__(16) u16 g_Khi[NBH*S_LEN*HD];
__device__ __align__(16) u16 g_Klo[NBH*S_LEN*HD];
__device__ __align__(16) u16 g_Vhi[NBH*S_LEN*HD];
__device__ __align__(16) u16 g_Vlo[NBH*S_LEN*HD];

__device__ __align__(16) __nv_bfloat16 g_wqkvT_hi[3*DMODEL*DMODEL];
__device__ __align__(16) __nv_bfloat16 g_wqkvT_lo[3*DMODEL*DMODEL];
__device__ __align__(16) __nv_bfloat16 g_woutT_hi[DMODEL*DMODEL];
__device__ __align__(16) __nv_bfloat16 g_woutT_lo[DMODEL*DMODEL];

#define NEGINF __int_as_float(0xff800000)

// ---------------------------------------------------------------------------
// helpers
// ---------------------------------------------------------------------------
__device__ __forceinline__ uint32_t cvt_bf16x2(float hi_elem, float lo_elem) {
    uint32_t r;
    asm("cvt.rn.bf16x2.f32 %0, %1, %2;" : "=r"(r) : "f"(hi_elem), "f"(lo_elem));
    return r;
}

__device__ __forceinline__ uint32_t smem_u32(const void* p) {
    uint32_t a;
    asm("{ .reg .u64 t; cvta.to.shared.u64 t, %1; cvt.u32.u64 %0, t; }" : "=r"(a) : "l"(p));
    return a;
}

// mma.sync m16n8k16 bf16 (arch-agnostic PTX, sm_80+)
__device__ __forceinline__ void mma16816(float* c, const uint32_t* a, const uint32_t* b) {
    asm volatile(
        "mma.sync.aligned.m16n8k16.row.col.f32.bf16.bf16.f32 "
        "{%0,%1,%2,%3}, {%4,%5,%6,%7}, {%8,%9}, {%0,%1,%2,%3};"
        : "+f"(c[0]), "+f"(c[1]), "+f"(c[2]), "+f"(c[3])
        : "r"(a[0]), "r"(a[1]), "r"(a[2]), "r"(a[3]), "r"(b[0]), "r"(b[1]));
}

// ldmatrix x4 (arch-agnostic PTX, sm_75+), addr = 32-bit shared address
#define LDSM_X4(r, addr) \
    asm volatile("ldmatrix.sync.aligned.m8n8.x4.shared.b16 {%0,%1,%2,%3}, [%4];" \
        : "=r"((r)[0]), "=r"((r)[1]), "=r"((r)[2]), "=r"((r)[3]) : "r"(addr))

// ---------------------------------------------------------------------------
// Position dtype detection + conversion
// ---------------------------------------------------------------------------
__global__ void detect_pos64(const int* __restrict__ raw, int n_words) {
    __shared__ int red[256];
    int acc = 0;
    for (int i = threadIdx.x; 2*i + 1 < n_words; i += 256)
        acc |= raw[2*i + 1];
    red[threadIdx.x] = acc;
    __syncthreads();
    for (int s1 = 128; s1 > 0; s1 >>= 1) {
        if (threadIdx.x < s1) red[threadIdx.x] |= red[threadIdx.x + s1];
        __syncthreads();
    }
    if (threadIdx.x == 0) g_is64 = (red[0] == 0) ? 1 : 0;
}

__global__ void convert_pos(const int* __restrict__ raw, int n) {
    int i = blockIdx.x * 256 + threadIdx.x;
    if (i >= n) return;
    int v = g_is64 ? raw[2*i] : raw[i];
    int ax = i % 3;
    int mx = (ax == 2) ? 7 : 31;
    v = v < 0 ? 0 : (v > mx ? mx : v);
    g_pos[i] = v;
}

__global__ void build_tables() {
    int t = threadIdx.x;            // 1024 threads
    int p = t >> 5, pos = t & 31;
    float inv;
    if (p < 10)      inv = powf(10000.0f, -(2.0f * p)        / 20.0f);
    else if (p < 20) inv = powf(10000.0f, -(2.0f * (p - 10)) / 20.0f);
    else             inv = powf(10000.0f, -(2.0f * (p - 20)) / 24.0f);
    float ang = (float)pos * inv;
    g_cos[t] = cosf(ang);
    g_sin[t] = sinf(ang);
}

// ---------------------------------------------------------------------------
// Transpose W[K][N] -> T[N][K] with bf16 hi/lo split.
// ---------------------------------------------------------------------------
__global__ void transpose_split(const float* __restrict__ W, int K, int N, int which) {
    __shared__ float tile[32][33];
    __nv_bfloat16* Thi = which ? g_woutT_hi : g_wqkvT_hi;
    __nv_bfloat16* Tlo = which ? g_woutT_lo : g_wqkvT_lo;
    int k0 = blockIdx.y * 32, n0 = blockIdx.x * 32;
    int x = threadIdx.x, y = threadIdx.y;
    #pragma unroll
    for (int i = y; i < 32; i += 8)
        tile[i][x] = W[(size_t)(k0 + i)*N + n0 + x];
    __syncthreads();
    #pragma unroll
    for (int i = y; i < 32; i += 8) {
        float f = tile[x][i];
        __nv_bfloat16 h = __float2bfloat16_rn(f);
        float r = f - __bfloat162float(h);
        size_t o = (size_t)(n0 + i)*K + k0 + x;
        Thi[o] = h;
        Tlo[o] = __float2bfloat16_rn(r);
    }
}

// ---------------------------------------------------------------------------
// mma.sync bf16x3 GEMM with in-kernel fp32 A split + ldmatrix fragments.
// C[M,N] = A[M,K] @ B^T  (B stored [N][K] K-major bf16 hi/lo).
// mode 1: A = Aext (hidden_states); epilogue = RoPE-fused scatter to
//         g_Q{hi,lo}/g_K{hi,lo} + split-scatter to g_V{hi,lo}.
// mode 2: A = g_attn; plain fp32 C write.
// ---------------------------------------------------------------------------
#define GK   1024
#define ASTR 40

__global__ __launch_bounds__(256)
void mma_gemm(const float* __restrict__ Aext, float* __restrict__ C,
              int N_total, int mode)
{
    __shared__ __nv_bfloat16 sAhi[128*ASTR];
    __shared__ __nv_bfloat16 sAlo[128*ASTR];
    __shared__ __nv_bfloat16 sBhi[128*ASTR];
    __shared__ __nv_bfloat16 sBlo[128*ASTR];

    const float* Afp = (mode == 1) ? Aext : (const float*)g_attn;
    const __nv_bfloat16 *Bhi, *Blo;
    if (mode == 1) { Bhi = g_wqkvT_hi; Blo = g_wqkvT_lo; }
    else           { Bhi = g_woutT_hi; Blo = g_woutT_lo; }

    const int tid  = threadIdx.x;
    const int lane = tid & 31;
    const int wid  = tid >> 5;
    const int warp_m = wid >> 2;        // 0..1
    const int warp_n = wid & 3;         // 0..3
    const int g = lane >> 2, t = lane & 3;
    const int m0 = blockIdx.y * 128;
    const int n0 = blockIdx.x * 128;

    const uint32_t bAhi = smem_u32(sAhi);
    const uint32_t bAlo = smem_u32(sAlo);
    const uint32_t bBhi = smem_u32(sBhi);
    const uint32_t bBlo = smem_u32(sBlo);

    // ldmatrix lane addressing
    const int lrow = lane & 7;
    const int lsel = lane >> 3;          // matrix id 0..3
    // A: mat0 rows0-7 k0 | mat1 rows8-15 k0 | mat2 rows0-7 k8 | mat3 rows8-15 k8
    const int a_roff = (lsel & 1)*8 + lrow;
    const int a_koff = (lsel >> 1)*8;
    // B: mat0 nt0 k0 | mat1 nt0 k8 | mat2 nt1 k0 | mat3 nt1 k8
    const int b_roff = (lsel >> 1)*8 + lrow;
    const int b_koff = (lsel & 1)*8;

    float acc[4][4][4];
    #pragma unroll
    for (int mt = 0; mt < 4; ++mt)
        #pragma unroll
        for (int nt = 0; nt < 4; ++nt)
            #pragma unroll
            for (int q = 0; q < 4; ++q) acc[mt][nt][q] = 0.0f;

    for (int k0 = 0; k0 < GK; k0 += 32) {
        // A: read fp32, split to bf16 hi/lo in-register (1024 float4, 4/thread)
        #pragma unroll
        for (int it = 0; it < 4; ++it) {
            int f = tid + it*256;
            int row = f >> 3, seg = f & 7;      // seg = 4-float group
            float4 v = *(const float4*)(Afp + (size_t)(m0 + row)*GK + k0 + seg*4);
            uint32_t h0 = cvt_bf16x2(v.y, v.x);
            uint32_t h1 = cvt_bf16x2(v.w, v.z);
            float e0 = __uint_as_float(h0 << 16), e1 = __uint_as_float(h0 & 0xffff0000u);
            float e2 = __uint_as_float(h1 << 16), e3 = __uint_as_float(h1 & 0xffff0000u);
            uint32_t l0 = cvt_bf16x2(v.y - e1, v.x - e0);
            uint32_t l1 = cvt_bf16x2(v.w - e3, v.z - e2);
            *(uint2*)(sAhi + row*ASTR + seg*4) = make_uint2(h0, h1);
            *(uint2*)(sAlo + row*ASTR + seg*4) = make_uint2(l0, l1);
        }
        // B: bf16 hi/lo direct (1024 uint4, 4/thread)
        #pragma unroll
        for (int it = 0; it < 4; ++it) {
            int f = tid + it*256;
            int arr = f >> 9;                   // 0 hi, 1 lo
            int idx = f & 511;
            int row = idx >> 2, seg = idx & 3;
            const __nv_bfloat16* src = (arr ? Blo : Bhi)
                + (size_t)(n0 + row)*GK + k0 + seg*8;
            *(uint4*)((arr ? sBlo : sBhi) + row*ASTR + seg*8) = *(const uint4*)src;
        }
        __syncthreads();

        #pragma unroll
        for (int kk = 0; kk < 2; ++kk) {
            uint32_t ah[4][4], al[4][4], bfr[2][2][4];   // bfr[hi/lo][ntp][4]
            #pragma unroll
            for (int mt = 0; mt < 4; ++mt) {
                uint32_t off = ((warp_m*64 + mt*16 + a_roff)*ASTR + kk*16 + a_koff)*2;
                LDSM_X4(ah[mt], bAhi + off);
                LDSM_X4(al[mt], bAlo + off);
            }
            #pragma unroll
            for (int ntp = 0; ntp < 2; ++ntp) {
                uint32_t off = ((warp_n*32 + ntp*16 + b_roff)*ASTR + kk*16 + b_koff)*2;
                LDSM_X4(bfr[0][ntp], bBhi + off);
                LDSM_X4(bfr[1][ntp], bBlo + off);
            }
            #pragma unroll
            for (int mt = 0; mt < 4; ++mt)
                #pragma unroll
                for (int nt = 0; nt < 4; ++nt) {
                    const uint32_t* bh2 = &bfr[0][nt >> 1][(nt & 1)*2];
                    const uint32_t* bl2 = &bfr[1][nt >> 1][(nt & 1)*2];
                    mma16816(acc[mt][nt], ah[mt], bh2);
                    mma16816(acc[mt][nt], ah[mt], bl2);
                    mma16816(acc[mt][nt], al[mt], bh2);
                }
        }
        __syncthreads();
    }

    if (mode == 1) {
        // RoPE-fused scatter. Thread owns cols n, n+1 with d even => RoPE pair.
        #pragma unroll
        for (int mt = 0; mt < 4; ++mt) {
            #pragma unroll
            for (int half = 0; half < 2; ++half) {
                int m = m0 + warp_m*64 + mt*16 + g + half*8;
                int bb = m >> 11, s = m & 2047;
                #pragma unroll
                for (int nt = 0; nt < 4; ++nt) {
                    int n = n0 + warp_n*32 + nt*8 + 2*t;
                    int sec = n >> 10;
                    int r = n & 1023;
                    int h = r >> 6, d = r & 63;
                    size_t idx = ((size_t)((bb*NHEAD + h)*S_LEN + s))*HD + d;
                    float x0 = acc[mt][nt][half*2 + 0];
                    float x1 = acc[mt][nt][half*2 + 1];
                    if (sec < 2) {
                        int p = d >> 1;
                        int ax = (p < 10) ? 0 : ((p < 20) ? 1 : 2);
                        int pos = g_pos[m*3 + ax];
                        float c  = g_cos[p*32 + pos];
                        float sn = g_sin[p*32 + pos];
                        float r0 = x0*c - x1*sn;
                        float r1 = x1*c + x0*sn;
                        uint32_t hv = cvt_bf16x2(r1, r0);
                        float eh0 = __uint_as_float(hv << 16);
                        float eh1 = __uint_as_float(hv & 0xffff0000u);
                        uint32_t lv = cvt_bf16x2(r1 - eh1, r0 - eh0);
                        if (sec == 0) {
                            *(uint32_t*)(g_Qhi + idx) = hv;
                            *(uint32_t*)(g_Qlo + idx) = lv;
                        } else {
                            *(uint32_t*)(g_Khi + idx) = hv;
                            *(uint32_t*)(g_Klo + idx) = lv;
                        }
                    } else {
                        uint32_t hv = cvt_bf16x2(x1, x0);
                        float eh0 = __uint_as_float(hv << 16);
                        float eh1 = __uint_as_float(hv & 0xffff0000u);
                        uint32_t lv = cvt_bf16x2(x1 - eh1, x0 - eh0);
                        *(uint32_t*)(g_Vhi + idx) = hv;
                        *(uint32_t*)(g_Vlo + idx) = lv;
                    }
                }
            }
        }
    } else {
        #pragma unroll
        for (int mt = 0; mt < 4; ++mt) {
            #pragma unroll
            for (int half = 0; half < 2; ++half) {
                int m = m0 + warp_m*64 + mt*16 + g + half*8;
                float* rowp = C + (size_t)m*N_total + n0 + warp_n*32 + 2*t;
                #pragma unroll
                for (int nt = 0; nt < 4; ++nt)
                    *(float2*)(rowp + nt*8) =
                        make_float2(acc[mt][nt][half*2 + 0], acc[mt][nt][half*2 + 1]);
            }
        }
    }
}

// ---------------------------------------------------------------------------
// Flash attention (causal) on mma.sync tensor cores, bf16x3 — R11, unchanged.
// ---------------------------------------------------------------------------
#define AS2 72
#define ATT_SMEM ((128*AS2*2 + 64*AS2*4) * 2)   // 73728 B

__global__ __launch_bounds__(256, 2)
void attention_mma() {
    extern __shared__ u16 sb[];
    u16* sQh = sb;
    u16* sQl = sQh + 128*AS2;
    u16* sKh = sQl + 128*AS2;
    u16* sKl = sKh + 64*AS2;
    u16* sVh = sKl + 64*AS2;
    u16* sVl = sVh + 64*AS2;

    const int tid  = threadIdx.x;
    const int lane = tid & 31;
    const int wid  = tid >> 5;
    const int g = lane >> 2, t = lane & 3;
    const int bh = blockIdx.y;
    const int qt = (int)gridDim.x - 1 - (int)blockIdx.x;

    const size_t hb = (size_t)bh * S_LEN;

    {
        const u16* Qh = g_Qhi + (hb + qt*128)*HD;
        const u16* Ql = g_Qlo + (hb + qt*128)*HD;
        #pragma unroll
        for (int it = 0; it < 4; ++it) {
            int f = tid + it*256;
            int row = f >> 3, seg = f & 7;
            *(uint4*)(sQh + row*AS2 + seg*8) = *(const uint4*)(Qh + row*HD + seg*8);
            *(uint4*)(sQl + row*AS2 + seg*8) = *(const uint4*)(Ql + row*HD + seg*8);
        }
    }

    float o[8][4];
    #pragma unroll
    for (int nt = 0; nt < 8; ++nt)
        #pragma unroll
        for (int q = 0; q < 4; ++q) o[nt][q] = 0.0f;
    float m0 = NEGINF, m1 = NEGINF, l0 = 0.0f, l1 = 0.0f;

    const int rowg = qt*128 + wid*16 + g;

    for (int kt = 0; kt <= 2*qt + 1; ++kt) {
        __syncthreads();
        {
            const u16* Kh = g_Khi + (hb + kt*64)*HD;
            const u16* Kl = g_Klo + (hb + kt*64)*HD;
            #pragma unroll
            for (int it = 0; it < 2; ++it) {
                int f = tid + it*256;
                int row = f >> 3, seg = f & 7;
                *(uint4*)(sKh + row*AS2 + seg*8) = *(const uint4*)(Kh + row*HD + seg*8);
                *(uint4*)(sKl + row*AS2 + seg*8) = *(const uint4*)(Kl + row*HD + seg*8);
            }
            const u16* Vh = g_Vhi + (hb + kt*64)*HD;
            const u16* Vl = g_Vlo + (hb + kt*64)*HD;
            #pragma unroll
            for (int it = 0; it < 2; ++it) {
                int f = tid + it*256;
                int key = f & 63, dseg = f >> 6;
                uint4 vh = *(const uint4*)(Vh + (key)*HD + dseg*8 + 0);
                uint4 vl = *(const uint4*)(Vl + (key)*HD + dseg*8 + 0);
                const u16* eh = (const u16*)&vh;
                const u16* el = (const u16*)&vl;
                #pragma unroll
                for (int j = 0; j < 8; ++j) {
                    sVh[(dseg*8 + j)*AS2 + key] = eh[j];
                    sVl[(dseg*8 + j)*AS2 + key] = el[j];
                }
            }
        }
        __syncthreads();

        float c[8][4];
        #pragma unroll
        for (int nt = 0; nt < 8; ++nt)
            #pragma unroll
            for (int q = 0; q < 4; ++q) c[nt][q] = 0.0f;

        #pragma unroll
        for (int kc = 0; kc < 4; ++kc) {
            const int ar = wid*16 + g;
            const int ko = kc*16 + 2*t;
            uint32_t ah[4], al[4];
            ah[0] = *(const uint32_t*)(sQh + ar*AS2 + ko);
            ah[1] = *(const uint32_t*)(sQh + (ar+8)*AS2 + ko);
            ah[2] = *(const uint32_t*)(sQh + ar*AS2 + ko + 8);
            ah[3] = *(const uint32_t*)(sQh + (ar+8)*AS2 + ko + 8);
            al[0] = *(const uint32_t*)(sQl + ar*AS2 + ko);
            al[1] = *(const uint32_t*)(sQl + (ar+8)*AS2 + ko);
            al[2] = *(const uint32_t*)(sQl + ar*AS2 + ko + 8);
            al[3] = *(const uint32_t*)(sQl + (ar+8)*AS2 + ko + 8);
            #pragma unroll
            for (int nt = 0; nt < 8; ++nt) {
                const int br = nt*8 + g;
                uint32_t bh2[2], bl2[2];
                bh2[0] = *(const uint32_t*)(sKh + br*AS2 + ko);
                bh2[1] = *(const uint32_t*)(sKh + br*AS2 + ko + 8);
                bl2[0] = *(const uint32_t*)(sKl + br*AS2 + ko);
                bl2[1] = *(const uint32_t*)(sKl + br*AS2 + ko + 8);
                mma16816(c[nt], ah, bh2);
                mma16816(c[nt], ah, bl2);
                mma16816(c[nt], al, bh2);
            }
        }

        if (kt >= 2*qt) {
            #pragma unroll
            for (int nt = 0; nt < 8; ++nt) {
                int col = kt*64 + nt*8 + 2*t;
                c[nt][0] = (col     > rowg    ) ? NEGINF : c[nt][0]*0.125f;
                c[nt][1] = (col + 1 > rowg    ) ? NEGINF : c[nt][1]*0.125f;
                c[nt][2] = (col     > rowg + 8) ? NEGINF : c[nt][2]*0.125f;
                c[nt][3] = (col + 1 > rowg + 8) ? NEGINF : c[nt][3]*0.125f;
            }
        } else {
            #pragma unroll
            for (int nt = 0; nt < 8; ++nt) {
                c[nt][0] *= 0.125f; c[nt][1] *= 0.125f;
                c[nt][2] *= 0.125f; c[nt][3] *= 0.125f;
            }
        }

        float rmax0 = NEGINF, rmax1 = NEGINF;
        #pragma unroll
        for (int nt = 0; nt < 8; ++nt) {
            rmax0 = fmaxf(rmax0, fmaxf(c[nt][0], c[nt][1]));
            rmax1 = fmaxf(rmax1, fmaxf(c[nt][2], c[nt][3]));
        }
        rmax0 = fmaxf(rmax0, __shfl_xor_sync(0xffffffffu, rmax0, 1));
        rmax0 = fmaxf(rmax0, __shfl_xor_sync(0xffffffffu, rmax0, 2));
        rmax1 = fmaxf(rmax1, __shfl_xor_sync(0xffffffffu, rmax1, 1));
        rmax1 = fmaxf(rmax1, __shfl_xor_sync(0xffffffffu, rmax1, 2));
        float mn0 = fmaxf(m0, rmax0), mn1 = fmaxf(m1, rmax1);
        float corr0 = __expf(m0 - mn0), corr1 = __expf(m1 - mn1);
        float rs0 = 0.0f, rs1 = 0.0f;
        #pragma unroll
        for (int nt = 0; nt < 8; ++nt) {
            c[nt][0] = __expf(c[nt][0] - mn0);
            c[nt][1] = __expf(c[nt][1] - mn0);
            c[nt][2] = __expf(c[nt][2] - mn1);
            c[nt][3] = __expf(c[nt][3] - mn1);
            rs0 += c[nt][0] + c[nt][1];
            rs1 += c[nt][2] + c[nt][3];
        }
        rs0 += __shfl_xor_sync(0xffffffffu, rs0, 1);
        rs0 += __shfl_xor_sync(0xffffffffu, rs0, 2);
        rs1 += __shfl_xor_sync(0xffffffffu, rs1, 1);
        rs1 += __shfl_xor_sync(0xffffffffu, rs1, 2);
        l0 = l0*corr0 + rs0;  m0 = mn0;
        l1 = l1*corr1 + rs1;  m1 = mn1;
        #pragma unroll
        for (int nt = 0; nt < 8; ++nt) {
            o[nt][0] *= corr0; o[nt][1] *= corr0;
            o[nt][2] *= corr1; o[nt][3] *= corr1;
        }

        #pragma unroll
        for (int kc = 0; kc < 4; ++kc) {
            const int j0 = 2*kc, j1 = 2*kc + 1;
            uint32_t ah[4], al[4];
            {
                uint32_t h0 = cvt_bf16x2(c[j0][1], c[j0][0]);
                uint32_t h1 = cvt_bf16x2(c[j0][3], c[j0][2]);
                uint32_t h2 = cvt_bf16x2(c[j1][1], c[j1][0]);
                uint32_t h3 = cvt_bf16x2(c[j1][3], c[j1][2]);
                ah[0] = h0; ah[1] = h1; ah[2] = h2; ah[3] = h3;
                al[0] = cvt_bf16x2(c[j0][1] - __uint_as_float(h0 & 0xffff0000u),
                                   c[j0][0] - __uint_as_float(h0 << 16));
                al[1] = cvt_bf16x2(c[j0][3] - __uint_as_float(h1 & 0xffff0000u),
                                   c[j0][2] - __uint_as_float(h1 << 16));
                al[2] = cvt_bf16x2(c[j1][1] - __uint_as_float(h2 & 0xffff0000u),
                                   c[j1][0] - __uint_as_float(h2 << 16));
                al[3] = cvt_bf16x2(c[j1][3] - __uint_as_float(h3 & 0xffff0000u),
                                   c[j1][2] - __uint_as_float(h3 << 16));
            }
            const int ko = kc*16 + 2*t;
            #pragma unroll
            for (int nt = 0; nt < 8; ++nt) {
                const int br = nt*8 + g;
                uint32_t bh2[2], bl2[2];
                bh2[0] = *(const uint32_t*)(sVh + br*AS2 + ko);
                bh2[1] = *(const uint32_t*)(sVh + br*AS2 + ko + 8);
                bl2[0] = *(const uint32_t*)(sVl + br*AS2 + ko);
                bl2[1] = *(const uint32_t*)(sVl + br*AS2 + ko + 8);
                mma16816(o[nt], ah, bh2);
                mma16816(o[nt], ah, bl2);
                mma16816(o[nt], al, bh2);
            }
        }
    }

    const int b = bh >> 4, h = bh & 15;
    const float inv0 = 1.0f / l0, inv1 = 1.0f / l1;
    const int sg0 = qt*128 + wid*16 + g;
    #pragma unroll
    for (int nt = 0; nt < 8; ++nt) {
        int col = h*HD + nt*8 + 2*t;
        *(float2*)(g_attn + (size_t)(b*S_LEN + sg0)*DMODEL + col) =
            make_float2(o[nt][0]*inv0, o[nt][1]*inv0);
        *(float2*)(g_attn + (size_t)(b*S_LEN + sg0 + 8)*DMODEL + col) =
            make_float2(o[nt][2]*inv1, o[nt][3]*inv1);
    }
}

// ---------------------------------------------------------------------------
extern "C" void kernel_launch(void* const* d_in, const int* in_sizes, int n_in,
                              void* d_out, int out_size) {
    const float* hs   = (const float*)d_in[0];   // [2,2048,1024]
    const float* wqkv = (const float*)d_in[1];   // [1024,3072]
    const float* wout = (const float*)d_in[2];   // [1024,1024]
    const int*   pos  = (const int*)  d_in[3];   // pos_xyz (int32 or int64)
    float* out = (float*)d_out;

    const int n_pos = NTOK * 3;

    detect_pos64<<<1, 256>>>(pos, n_pos);
    convert_pos<<<(n_pos + 255)/256, 256>>>(pos, n_pos);
    build_tables<<<1, 1024>>>();

    // Weight transposes + bf16 splits
    transpose_split<<<dim3(3*DMODEL/32, DMODEL/32), dim3(32, 8)>>>(wqkv, DMODEL, 3*DMODEL, 0);
    transpose_split<<<dim3(DMODEL/32, DMODEL/32), dim3(32, 8)>>>(wout, DMODEL, DMODEL, 1);

    // QKV projection: in-kernel A split, RoPE-fused epilogue
    mma_gemm<<<dim3(3*DMODEL/128, NTOK/128), 256>>>(hs, nullptr, 3*DMODEL, 1);

    // Attention (tensor cores)
    cudaFuncSetAttribute(attention_mma,
                         cudaFuncAttributeMaxDynamicSharedMemorySize, ATT_SMEM);
    attention_mma<<<dim3(S_LEN/128, NBH), 256, ATT_SMEM>>>();

    // Output projection: A = g_attn (in-kernel split)
    mma_gemm<<<dim3(DMODEL/128, NTOK/128), 256>>>(nullptr, out, DMODEL, 2);
}

// round 13
// speedup vs baseline: 2.8268x; 1.1087x over previous
#include <cuda_runtime.h>
#include <cuda_bf16.h>
#include <math.h>
#include <stdint.h>

// Problem constants
#define BATCH   2
#define S_LEN   2048
#define NHEAD   16
#define HD      64
#define DMODEL  1024   // NHEAD*HD
#define NPAIRS  32     // HD/2
#define NTOK    (BATCH*S_LEN)   // 4096
#define NBH     (BATCH*NHEAD)   // 32

typedef unsigned long long ull;
typedef unsigned short u16;

// Scratch (device globals — no allocation allowed).
// Only referenced from device code (GB300 host-shadow/ATS pitfall).
__device__ __align__(16) float g_attn[NTOK*DMODEL];
__device__ int   g_pos[NTOK*3];
__device__ int   g_is64;
__device__ float g_cos[NPAIRS*32];
__device__ float g_sin[NPAIRS*32];

// bf16 hi/lo split operands (raw u16 bits)
__device__ __align__(16) u16 g_Qhi[NBH*S_LEN*HD];
__device__ __align__(16) u16 g_Qlo[NBH*S_LEN*HD];
__device__ __align__(16) u16 g_Khi[NBH*S_LEN*HD];
__device__ __align__(16) u16 g_Klo[NBH*S_LEN*HD];
__device__ __align__(16) u16 g_Vhi[NBH*S_LEN*HD];
__device__ __align__(16) u16 g_Vlo[NBH*S_LEN*HD];

__device__ __align__(16) __nv_bfloat16 g_wqkvT_hi[3*DMODEL*DMODEL];
__device__ __align__(16) __nv_bfloat16 g_wqkvT_lo[3*DMODEL*DMODEL];
__device__ __align__(16) __nv_bfloat16 g_woutT_hi[DMODEL*DMODEL];
__device__ __align__(16) __nv_bfloat16 g_woutT_lo[DMODEL*DMODEL];

#define NEGINF __int_as_float(0xff800000)

// ---------------------------------------------------------------------------
// helpers
// ---------------------------------------------------------------------------
__device__ __forceinline__ uint32_t cvt_bf16x2(float hi_elem, float lo_elem) {
    uint32_t r;
    asm("cvt.rn.bf16x2.f32 %0, %1, %2;" : "=r"(r) : "f"(hi_elem), "f"(lo_elem));
    return r;
}

__device__ __forceinline__ uint32_t smem_u32(const void* p) {
    uint32_t a;
    asm("{ .reg .u64 t; cvta.to.shared.u64 t, %1; cvt.u32.u64 %0, t; }" : "=r"(a) : "l"(p));
    return a;
}

// mma.sync m16n8k16 bf16 (arch-agnostic PTX, sm_80+)
__device__ __forceinline__ void mma16816(float* c, const uint32_t* a, const uint32_t* b) {
    asm volatile(
        "mma.sync.aligned.m16n8k16.row.col.f32.bf16.bf16.f32 "
        "{%0,%1,%2,%3}, {%4,%5,%6,%7}, {%8,%9}, {%0,%1,%2,%3};"
        : "+f"(c[0]), "+f"(c[1]), "+f"(c[2]), "+f"(c[3])
        : "r"(a[0]), "r"(a[1]), "r"(a[2]), "r"(a[3]), "r"(b[0]), "r"(b[1]));
}

// ldmatrix x4 (sm_75+), addr = 32-bit shared address
#define LDSM_X4(r, addr) \
    asm volatile("ldmatrix.sync.aligned.m8n8.x4.shared.b16 {%0,%1,%2,%3}, [%4];" \
        : "=r"((r)[0]), "=r"((r)[1]), "=r"((r)[2]), "=r"((r)[3]) : "r"(addr))
#define LDSM_X4_T(r, addr) \
    asm volatile("ldmatrix.sync.aligned.m8n8.x4.trans.shared.b16 {%0,%1,%2,%3}, [%4];" \
        : "=r"((r)[0]), "=r"((r)[1]), "=r"((r)[2]), "=r"((r)[3]) : "r"(addr))

// cp.async (sm_80+)
#define CP_ASYNC16(daddr, gptr) \
    asm volatile("cp.async.ca.shared.global [%0], [%1], 16;" \
        :: "r"(daddr), "l"(gptr) : "memory")
#define CP_COMMIT() asm volatile("cp.async.commit_group;" ::: "memory")
#define CP_WAIT0()  asm volatile("cp.async.wait_group 0;" ::: "memory")

// ---------------------------------------------------------------------------
// Position dtype detection + conversion
// ---------------------------------------------------------------------------
__global__ void detect_pos64(const int* __restrict__ raw, int n_words) {
    __shared__ int red[256];
    int acc = 0;
    for (int i = threadIdx.x; 2*i + 1 < n_words; i += 256)
        acc |= raw[2*i + 1];
    red[threadIdx.x] = acc;
    __syncthreads();
    for (int s1 = 128; s1 > 0; s1 >>= 1) {
        if (threadIdx.x < s1) red[threadIdx.x] |= red[threadIdx.x + s1];
        __syncthreads();
    }
    if (threadIdx.x == 0) g_is64 = (red[0] == 0) ? 1 : 0;
}

__global__ void convert_pos(const int* __restrict__ raw, int n) {
    int i = blockIdx.x * 256 + threadIdx.x;
    if (i >= n) return;
    int v = g_is64 ? raw[2*i] : raw[i];
    int ax = i % 3;
    int mx = (ax == 2) ? 7 : 31;
    v = v < 0 ? 0 : (v > mx ? mx : v);
    g_pos[i] = v;
}

__global__ void build_tables() {
    int t = threadIdx.x;            // 1024 threads
    int p = t >> 5, pos = t & 31;
    float inv;
    if (p < 10)      inv = powf(10000.0f, -(2.0f * p)        / 20.0f);
    else if (p < 20) inv = powf(10000.0f, -(2.0f * (p - 10)) / 20.0f);
    else             inv = powf(10000.0f, -(2.0f * (p - 20)) / 24.0f);
    float ang = (float)pos * inv;
    g_cos[t] = cosf(ang);
    g_sin[t] = sinf(ang);
}

// ---------------------------------------------------------------------------
// Transpose W[K][N] -> T[N][K] with bf16 hi/lo split.
// ---------------------------------------------------------------------------
__global__ void transpose_split(const float* __restrict__ W, int K, int N, int which) {
    __shared__ float tile[32][33];
    __nv_bfloat16* Thi = which ? g_woutT_hi : g_wqkvT_hi;
    __nv_bfloat16* Tlo = which ? g_woutT_lo : g_wqkvT_lo;
    int k0 = blockIdx.y * 32, n0 = blockIdx.x * 32;
    int x = threadIdx.x, y = threadIdx.y;
    #pragma unroll
    for (int i = y; i < 32; i += 8)
        tile[i][x] = W[(size_t)(k0 + i)*N + n0 + x];
    __syncthreads();
    #pragma unroll
    for (int i = y; i < 32; i += 8) {
        float f = tile[x][i];
        __nv_bfloat16 h = __float2bfloat16_rn(f);
        float r = f - __bfloat162float(h);
        size_t o = (size_t)(n0 + i)*K + k0 + x;
        Thi[o] = h;
        Tlo[o] = __float2bfloat16_rn(r);
    }
}

// ---------------------------------------------------------------------------
// mma.sync bf16x3 GEMM, DOUBLE-BUFFERED (cp.async B, register-prefetch A).
// C[M,N] = A[M,K] @ B^T  (B stored [N][K] K-major bf16 hi/lo).
// mode 1: A = Aext (hidden_states); RoPE-fused scatter epilogue.
// mode 2: A = g_attn; plain fp32 C write.
// Dynamic smem: 2 stages x (Ahi|Alo|Bhi|Blo) x 128 x ASTR u16 = 81920 B.
// ---------------------------------------------------------------------------
#define GK   1024
#define ASTR 40
#define STG_BYTES (4*128*ASTR*2)      // 40960 B per stage
#define GEMM_SMEM (2*STG_BYTES)       // 81920 B

__global__ __launch_bounds__(256)
void mma_gemm(const float* __restrict__ Aext, float* __restrict__ C,
              int N_total, int mode)
{
    extern __shared__ u16 dsm[];

    const float* Afp = (mode == 1) ? Aext : (const float*)g_attn;
    const __nv_bfloat16 *Bhi, *Blo;
    if (mode == 1) { Bhi = g_wqkvT_hi; Blo = g_wqkvT_lo; }
    else           { Bhi = g_woutT_hi; Blo = g_woutT_lo; }

    const int tid  = threadIdx.x;
    const int lane = tid & 31;
    const int wid  = tid >> 5;
    const int warp_m = wid >> 2;        // 0..1
    const int warp_n = wid & 3;         // 0..3
    const int g = lane >> 2, t = lane & 3;
    const int m0 = blockIdx.y * 128;
    const int n0 = blockIdx.x * 128;

    const uint32_t dbase = smem_u32(dsm);

    // ldmatrix lane addressing
    const int lrow = lane & 7;
    const int lsel = lane >> 3;
    const int a_roff = (lsel & 1)*8 + lrow;
    const int a_koff = (lsel >> 1)*8;
    const int b_roff = (lsel >> 1)*8 + lrow;
    const int b_koff = (lsel & 1)*8;

    // per-thread load coords
    const int a_row = tid >> 3;                 // with +32-row steps per it? no:
    // A: f = tid + it*256 (0..1023), row = f>>3 (0..127), seg = f&7 (4-float groups)
    // B: f = tid + it*256 (0..1023), arr = f>>9, idx=f&511, row=idx>>2, seg=idx&3

    float4 apref[4];

    auto loadA = [&](int ch) {
        #pragma unroll
        for (int it = 0; it < 4; ++it) {
            int f = tid + it*256;
            int row = f >> 3, seg = f & 7;
            apref[it] = *(const float4*)(Afp + (size_t)(m0 + row)*GK + ch*32 + seg*4);
        }
    };
    auto storeA = [&](int st) {
        u16* sA = dsm + (size_t)st*(STG_BYTES/2);
        #pragma unroll
        for (int it = 0; it < 4; ++it) {
            int f = tid + it*256;
            int row = f >> 3, seg = f & 7;
            float4 v = apref[it];
            uint32_t h0 = cvt_bf16x2(v.y, v.x);
            uint32_t h1 = cvt_bf16x2(v.w, v.z);
            float e0 = __uint_as_float(h0 << 16), e1 = __uint_as_float(h0 & 0xffff0000u);
            float e2 = __uint_as_float(h1 << 16), e3 = __uint_as_float(h1 & 0xffff0000u);
            uint32_t l0 = cvt_bf16x2(v.y - e1, v.x - e0);
            uint32_t l1 = cvt_bf16x2(v.w - e3, v.z - e2);
            *(uint2*)(sA + row*ASTR + seg*4) = make_uint2(h0, h1);              // Ahi
            *(uint2*)(sA + 5120 + row*ASTR + seg*4) = make_uint2(l0, l1);      // Alo
        }
    };
    auto loadB = [&](int st, int ch) {
        uint32_t bB = dbase + st*STG_BYTES + 20480;    // Bhi offset in bytes
        #pragma unroll
        for (int it = 0; it < 4; ++it) {
            int f = tid + it*256;
            int arr = f >> 9;
            int idx = f & 511;
            int row = idx >> 2, seg = idx & 3;
            const __nv_bfloat16* src = (arr ? Blo : Bhi)
                + (size_t)(n0 + row)*GK + ch*32 + seg*8;
            uint32_t daddr = bB + arr*10240 + (row*ASTR + seg*8)*2;
            CP_ASYNC16(daddr, src);
        }
        CP_COMMIT();
    };

    float acc[4][4][4];
    #pragma unroll
    for (int mt = 0; mt < 4; ++mt)
        #pragma unroll
        for (int nt = 0; nt < 4; ++nt)
            #pragma unroll
            for (int q = 0; q < 4; ++q) acc[mt][nt][q] = 0.0f;

    // prologue: stage 0 <- chunk 0
    loadA(0);
    loadB(0, 0);
    storeA(0);
    CP_WAIT0();
    __syncthreads();

    for (int ch = 0; ch < GK/32; ++ch) {
        const int cur = ch & 1;
        const int nxt = 1 - cur;
        if (ch + 1 < GK/32) {
            loadA(ch + 1);
            loadB(nxt, ch + 1);
        }

        // compute on stage cur
        {
            const uint32_t sbase = dbase + cur*STG_BYTES;
            const uint32_t bAhi = sbase;
            const uint32_t bAlo = sbase + 10240;
            const uint32_t bBhi = sbase + 20480;
            const uint32_t bBlo = sbase + 30720;
            #pragma unroll
            for (int kk = 0; kk < 2; ++kk) {
                uint32_t ah[4][4], al[4][4], bfr[2][2][4];
                #pragma unroll
                for (int mt = 0; mt < 4; ++mt) {
                    uint32_t off = ((warp_m*64 + mt*16 + a_roff)*ASTR + kk*16 + a_koff)*2;
                    LDSM_X4(ah[mt], bAhi + off);
                    LDSM_X4(al[mt], bAlo + off);
                }
                #pragma unroll
                for (int ntp = 0; ntp < 2; ++ntp) {
                    uint32_t off = ((warp_n*32 + ntp*16 + b_roff)*ASTR + kk*16 + b_koff)*2;
                    LDSM_X4(bfr[0][ntp], bBhi + off);
                    LDSM_X4(bfr[1][ntp], bBlo + off);
                }
                #pragma unroll
                for (int mt = 0; mt < 4; ++mt)
                    #pragma unroll
                    for (int nt = 0; nt < 4; ++nt) {
                        const uint32_t* bh2 = &bfr[0][nt >> 1][(nt & 1)*2];
                        const uint32_t* bl2 = &bfr[1][nt >> 1][(nt & 1)*2];
                        mma16816(acc[mt][nt], ah[mt], bh2);
                        mma16816(acc[mt][nt], ah[mt], bl2);
                        mma16816(acc[mt][nt], al[mt], bh2);
                    }
            }
        }

        if (ch + 1 < GK/32) {
            storeA(nxt);
            CP_WAIT0();
        }
        __syncthreads();
    }

    if (mode == 1) {
        // RoPE-fused scatter. Thread owns cols n, n+1 with d even => RoPE pair.
        #pragma unroll
        for (int mt = 0; mt < 4; ++mt) {
            #pragma unroll
            for (int half = 0; half < 2; ++half) {
                int m = m0 + warp_m*64 + mt*16 + g + half*8;
                int bb = m >> 11, s = m & 2047;
                #pragma unroll
                for (int nt = 0; nt < 4; ++nt) {
                    int n = n0 + warp_n*32 + nt*8 + 2*t;
                    int sec = n >> 10;
                    int r = n & 1023;
                    int h = r >> 6, d = r & 63;
                    size_t idx = ((size_t)((bb*NHEAD + h)*S_LEN + s))*HD + d;
                    float x0 = acc[mt][nt][half*2 + 0];
                    float x1 = acc[mt][nt][half*2 + 1];
                    if (sec < 2) {
                        int p = d >> 1;
                        int ax = (p < 10) ? 0 : ((p < 20) ? 1 : 2);
                        int pos = g_pos[m*3 + ax];
                        float c  = g_cos[p*32 + pos];
                        float sn = g_sin[p*32 + pos];
                        float r0 = x0*c - x1*sn;
                        float r1 = x1*c + x0*sn;
                        uint32_t hv = cvt_bf16x2(r1, r0);
                        float eh0 = __uint_as_float(hv << 16);
                        float eh1 = __uint_as_float(hv & 0xffff0000u);
                        uint32_t lv = cvt_bf16x2(r1 - eh1, r0 - eh0);
                        if (sec == 0) {
                            *(uint32_t*)(g_Qhi + idx) = hv;
                            *(uint32_t*)(g_Qlo + idx) = lv;
                        } else {
                            *(uint32_t*)(g_Khi + idx) = hv;
                            *(uint32_t*)(g_Klo + idx) = lv;
                        }
                    } else {
                        uint32_t hv = cvt_bf16x2(x1, x0);
                        float eh0 = __uint_as_float(hv << 16);
                        float eh1 = __uint_as_float(hv & 0xffff0000u);
                        uint32_t lv = cvt_bf16x2(x1 - eh1, x0 - eh0);
                        *(uint32_t*)(g_Vhi + idx) = hv;
                        *(uint32_t*)(g_Vlo + idx) = lv;
                    }
                }
            }
        }
    } else {
        #pragma unroll
        for (int mt = 0; mt < 4; ++mt) {
            #pragma unroll
            for (int half = 0; half < 2; ++half) {
                int m = m0 + warp_m*64 + mt*16 + g + half*8;
                float* rowp = C + (size_t)m*N_total + n0 + warp_n*32 + 2*t;
                #pragma unroll
                for (int nt = 0; nt < 4; ++nt)
                    *(float2*)(rowp + nt*8) =
                        make_float2(acc[mt][nt][half*2 + 0], acc[mt][nt][half*2 + 1]);
            }
        }
    }
}

// ---------------------------------------------------------------------------
// Flash attention (causal) on mma.sync tensor cores, bf16x3.
// V kept natural [key][d]; PV B-fragments via ldmatrix.x4.trans (conflict-free
// with AS2=72: row stride 36 words -> 4r mod 32 covers all banks).
// ---------------------------------------------------------------------------
#define AS2 72
#define ATT_SMEM ((128*AS2*2 + 64*AS2*4) * 2)   // 73728 B

__global__ __launch_bounds__(256, 2)
void attention_mma() {
    extern __shared__ u16 sb[];
    u16* sQh = sb;
    u16* sQl = sQh + 128*AS2;
    u16* sKh = sQl + 128*AS2;
    u16* sKl = sKh + 64*AS2;
    u16* sVh = sKl + 64*AS2;    // natural [key][d]
    u16* sVl = sVh + 64*AS2;

    const int tid  = threadIdx.x;
    const int lane = tid & 31;
    const int wid  = tid >> 5;
    const int g = lane >> 2, t = lane & 3;
    const int lrow = lane & 7, lsel = lane >> 3;
    const int bh = blockIdx.y;
    const int qt = (int)gridDim.x - 1 - (int)blockIdx.x;

    const size_t hb = (size_t)bh * S_LEN;
    const uint32_t bVh = smem_u32(sVh);
    const uint32_t bVl = smem_u32(sVl);

    {
        const u16* Qh = g_Qhi + (hb + qt*128)*HD;
        const u16* Ql = g_Qlo + (hb + qt*128)*HD;
        #pragma unroll
        for (int it = 0; it < 4; ++it) {
            int f = tid + it*256;
            int row = f >> 3, seg = f & 7;
            *(uint4*)(sQh + row*AS2 + seg*8) = *(const uint4*)(Qh + row*HD + seg*8);
            *(uint4*)(sQl + row*AS2 + seg*8) = *(const uint4*)(Ql + row*HD + seg*8);
        }
    }

    float o[8][4];
    #pragma unroll
    for (int nt = 0; nt < 8; ++nt)
        #pragma unroll
        for (int q = 0; q < 4; ++q) o[nt][q] = 0.0f;
    float m0 = NEGINF, m1 = NEGINF, l0 = 0.0f, l1 = 0.0f;

    const int rowg = qt*128 + wid*16 + g;

    for (int kt = 0; kt <= 2*qt + 1; ++kt) {
        __syncthreads();
        {
            const u16* Kh = g_Khi + (hb + kt*64)*HD;
            const u16* Kl = g_Klo + (hb + kt*64)*HD;
            const u16* Vh = g_Vhi + (hb + kt*64)*HD;
            const u16* Vl = g_Vlo + (hb + kt*64)*HD;
            #pragma unroll
            for (int it = 0; it < 2; ++it) {
                int f = tid + it*256;
                int row = f >> 3, seg = f & 7;
                *(uint4*)(sKh + row*AS2 + seg*8) = *(const uint4*)(Kh + row*HD + seg*8);
                *(uint4*)(sKl + row*AS2 + seg*8) = *(const uint4*)(Kl + row*HD + seg*8);
                *(uint4*)(sVh + row*AS2 + seg*8) = *(const uint4*)(Vh + row*HD + seg*8);
                *(uint4*)(sVl + row*AS2 + seg*8) = *(const uint4*)(Vl + row*HD + seg*8);
            }
        }
        __syncthreads();

        float c[8][4];
        #pragma unroll
        for (int nt = 0; nt < 8; ++nt)
            #pragma unroll
            for (int q = 0; q < 4; ++q) c[nt][q] = 0.0f;

        #pragma unroll
        for (int kc = 0; kc < 4; ++kc) {
            const int ar = wid*16 + g;
            const int ko = kc*16 + 2*t;
            uint32_t ah[4], al[4];
            ah[0] = *(const uint32_t*)(sQh + ar*AS2 + ko);
            ah[1] = *(const uint32_t*)(sQh + (ar+8)*AS2 + ko);
            ah[2] = *(const uint32_t*)(sQh + ar*AS2 + ko + 8);
            ah[3] = *(const uint32_t*)(sQh + (ar+8)*AS2 + ko + 8);
            al[0] = *(const uint32_t*)(sQl + ar*AS2 + ko);
            al[1] = *(const uint32_t*)(sQl + (ar+8)*AS2 + ko);
            al[2] = *(const uint32_t*)(sQl + ar*AS2 + ko + 8);
            al[3] = *(const uint32_t*)(sQl + (ar+8)*AS2 + ko + 8);
            #pragma unroll
            for (int nt = 0; nt < 8; ++nt) {
                const int br = nt*8 + g;
                uint32_t bh2[2], bl2[2];
                bh2[0] = *(const uint32_t*)(sKh + br*AS2 + ko);
                bh2[1] = *(const uint32_t*)(sKh + br*AS2 + ko + 8);
                bl2[0] = *(const uint32_t*)(sKl + br*AS2 + ko);
                bl2[1] = *(const uint32_t*)(sKl + br*AS2 + ko + 8);
                mma16816(c[nt], ah, bh2);
                mma16816(c[nt], ah, bl2);
                mma16816(c[nt], al, bh2);
            }
        }

        if (kt >= 2*qt) {
            #pragma unroll
            for (int nt = 0; nt < 8; ++nt) {
                int col = kt*64 + nt*8 + 2*t;
                c[nt][0] = (col     > rowg    ) ? NEGINF : c[nt][0]*0.125f;
                c[nt][1] = (col + 1 > rowg    ) ? NEGINF : c[nt][1]*0.125f;
                c[nt][2] = (col     > rowg + 8) ? NEGINF : c[nt][2]*0.125f;
                c[nt][3] = (col + 1 > rowg + 8) ? NEGINF : c[nt][3]*0.125f;
            }
        } else {
            #pragma unroll
            for (int nt = 0; nt < 8; ++nt) {
                c[nt][0] *= 0.125f; c[nt][1] *= 0.125f;
                c[nt][2] *= 0.125f; c[nt][3] *= 0.125f;
            }
        }

        float rmax0 = NEGINF, rmax1 = NEGINF;
        #pragma unroll
        for (int nt = 0; nt < 8; ++nt) {
            rmax0 = fmaxf(rmax0, fmaxf(c[nt][0], c[nt][1]));
            rmax1 = fmaxf(rmax1, fmaxf(c[nt][2], c[nt][3]));
        }
        rmax0 = fmaxf(rmax0, __shfl_xor_sync(0xffffffffu, rmax0, 1));
        rmax0 = fmaxf(rmax0, __shfl_xor_sync(0xffffffffu, rmax0, 2));
        rmax1 = fmaxf(rmax1, __shfl_xor_sync(0xffffffffu, rmax1, 1));
        rmax1 = fmaxf(rmax1, __shfl_xor_sync(0xffffffffu, rmax1, 2));
        float mn0 = fmaxf(m0, rmax0), mn1 = fmaxf(m1, rmax1);
        float corr0 = __expf(m0 - mn0), corr1 = __expf(m1 - mn1);
        float rs0 = 0.0f, rs1 = 0.0f;
        #pragma unroll
        for (int nt = 0; nt < 8; ++nt) {
            c[nt][0] = __expf(c[nt][0] - mn0);
            c[nt][1] = __expf(c[nt][1] - mn0);
            c[nt][2] = __expf(c[nt][2] - mn1);
            c[nt][3] = __expf(c[nt][3] - mn1);
            rs0 += c[nt][0] + c[nt][1];
            rs1 += c[nt][2] + c[nt][3];
        }
        rs0 += __shfl_xor_sync(0xffffffffu, rs0, 1);
        rs0 += __shfl_xor_sync(0xffffffffu, rs0, 2);
        rs1 += __shfl_xor_sync(0xffffffffu, rs1, 1);
        rs1 += __shfl_xor_sync(0xffffffffu, rs1, 2);
        l0 = l0*corr0 + rs0;  m0 = mn0;
        l1 = l1*corr1 + rs1;  m1 = mn1;
        #pragma unroll
        for (int nt = 0; nt < 8; ++nt) {
            o[nt][0] *= corr0; o[nt][1] *= corr0;
            o[nt][2] *= corr1; o[nt][3] *= corr1;
        }

        // O += P V : P repacked in-register (hi/lo), V via ldmatrix.trans
        #pragma unroll
        for (int kc = 0; kc < 4; ++kc) {
            const int j0 = 2*kc, j1 = 2*kc + 1;
            uint32_t ah[4], al[4];
            {
                uint32_t h0 = cvt_bf16x2(c[j0][1], c[j0][0]);
                uint32_t h1 = cvt_bf16x2(c[j0][3], c[j0][2]);
                uint32_t h2 = cvt_bf16x2(c[j1][1], c[j1][0]);
                uint32_t h3 = cvt_bf16x2(c[j1][3], c[j1][2]);
                ah[0] = h0; ah[1] = h1; ah[2] = h2; ah[3] = h3;
                al[0] = cvt_bf16x2(c[j0][1] - __uint_as_float(h0 & 0xffff0000u),
                                   c[j0][0] - __uint_as_float(h0 << 16));
                al[1] = cvt_bf16x2(c[j0][3] - __uint_as_float(h1 & 0xffff0000u),
                                   c[j0][2] - __uint_as_float(h1 << 16));
                al[2] = cvt_bf16x2(c[j1][1] - __uint_as_float(h2 & 0xffff0000u),
                                   c[j1][0] - __uint_as_float(h2 << 16));
                al[3] = cvt_bf16x2(c[j1][3] - __uint_as_float(h3 & 0xffff0000u),
                                   c[j1][2] - __uint_as_float(h3 << 16));
            }
            // ldmatrix.trans address: row = kc*16 + (lsel&1)*8 + lrow,
            //                         col = ntp*16 + (lsel>>1)*8
            const uint32_t roff = (kc*16 + (lsel & 1)*8 + lrow)*AS2 + (lsel >> 1)*8;
            #pragma unroll
            for (int ntp = 0; ntp < 4; ++ntp) {
                uint32_t off = (roff + ntp*16)*2;
                uint32_t bh4[4], bl4[4];
                LDSM_X4_T(bh4, bVh + off);
                LDSM_X4_T(bl4, bVl + off);
                mma16816(o[2*ntp + 0], ah, bh4 + 0);
                mma16816(o[2*ntp + 0], ah, bl4 + 0);
                mma16816(o[2*ntp + 0], al, bh4 + 0);
                mma16816(o[2*ntp + 1], ah, bh4 + 2);
                mma16816(o[2*ntp + 1], ah, bl4 + 2);
                mma16816(o[2*ntp + 1], al, bh4 + 2);
            }
        }
    }

    const int b = bh >> 4, h = bh & 15;
    const float inv0 = 1.0f / l0, inv1 = 1.0f / l1;
    const int sg0 = qt*128 + wid*16 + g;
    #pragma unroll
    for (int nt = 0; nt < 8; ++nt) {
        int col = h*HD + nt*8 + 2*t;
        *(float2*)(g_attn + (size_t)(b*S_LEN + sg0)*DMODEL + col) =
            make_float2(o[nt][0]*inv0, o[nt][1]*inv0);
        *(float2*)(g_attn + (size_t)(b*S_LEN + sg0 + 8)*DMODEL + col) =
            make_float2(o[nt][2]*inv1, o[nt][3]*inv1);
    }
}

// ---------------------------------------------------------------------------
extern "C" void kernel_launch(void* const* d_in, const int* in_sizes, int n_in,
                              void* d_out, int out_size) {
    const float* hs   = (const float*)d_in[0];   // [2,2048,1024]
    const float* wqkv = (const float*)d_in[1];   // [1024,3072]
    const float* wout = (const float*)d_in[2];   // [1024,1024]
    const int*   pos  = (const int*)  d_in[3];   // pos_xyz (int32 or int64)
    float* out = (float*)d_out;

    const int n_pos = NTOK * 3;

    detect_pos64<<<1, 256>>>(pos, n_pos);
    convert_pos<<<(n_pos + 255)/256, 256>>>(pos, n_pos);
    build_tables<<<1, 1024>>>();

    // Weight transposes + bf16 splits
    transpose_split<<<dim3(3*DMODEL/32, DMODEL/32), dim3(32, 8)>>>(wqkv, DMODEL, 3*DMODEL, 0);
    transpose_split<<<dim3(DMODEL/32, DMODEL/32), dim3(32, 8)>>>(wout, DMODEL, DMODEL, 1);

    cudaFuncSetAttribute(mma_gemm, cudaFuncAttributeMaxDynamicSharedMemorySize, GEMM_SMEM);

    // QKV projection: double-buffered, in-kernel A split, RoPE-fused epilogue
    mma_gemm<<<dim3(3*DMODEL/128, NTOK/128), 256, GEMM_SMEM>>>(hs, nullptr, 3*DMODEL, 1);

    // Attention (tensor cores)
    cudaFuncSetAttribute(attention_mma,
                         cudaFuncAttributeMaxDynamicSharedMemorySize, ATT_SMEM);
    attention_mma<<<dim3(S_LEN/128, NBH), 256, ATT_SMEM>>>();

    // Output projection
    mma_gemm<<<dim3(DMODEL/128, NTOK/128), 256, GEMM_SMEM>>>(nullptr, out, DMODEL, 2);
}